// round 3
// baseline (speedup 1.0000x reference)
#include <cuda_runtime.h>
#include <cuda_bf16.h>
#include <math.h>

// Problem dims (fixed)
#define BB 2
#define LL 2048
#define DD 1024
#define SS 16
#define EE 4
#define HH 2048
#define NN (BB*LL)   // 4096

// ---------------- scratch (device globals; no allocation allowed) ----------------
__device__ float g_delta[NN*DD];
__device__ float g_Bm[NN*SS];
__device__ float g_Cm[NN*SS];
__device__ float g_ssm[NN*DD];
__device__ float g_acc[NN*DD];
__device__ int   g_cnt[EE];
__device__ int   g_list[EE*NN];
__device__ float g_cw[EE*NN];
__device__ float g_G[NN*HH];
__device__ float g_U[NN*HH];
__device__ float g_act[NN*HH];

__device__ __forceinline__ float softplusf(float z) {
    return (z > 20.f) ? z : log1pf(__expf(z));
}

// ---------------- zero counts ----------------
__global__ void zero_counts() {
    if (threadIdx.x < EE) g_cnt[threadIdx.x] = 0;
}

// ---------------- generic 64x64x16 SIMT GEMM ----------------
// MODE 0: C1[gr,:] = softplus(A@B1 + bias)       (direct rows, M fixed)
// MODE 1: C1 = gather(A)@B1, C2 = gather(A)@B2   (rows gathered via rowidx, M=*cntp)
// MODE 2: C1[rowidx[gr],:] += A@B1               (rows scattered, M=*cntp)
template<int MODE>
__global__ __launch_bounds__(256)
void gemm64(const float* __restrict__ A, const float* __restrict__ B1,
            const float* __restrict__ B2, float* __restrict__ C1,
            float* __restrict__ C2, const float* __restrict__ bias,
            int M, int Ncols, int K,
            const int* __restrict__ rowidx, const int* __restrict__ cntp)
{
    if (MODE != 0) M = *cntp;
    int mblk = blockIdx.y, nblk = blockIdx.x;
    if (mblk * 64 >= M) return;

    __shared__ float As[16][64];
    __shared__ float Bs1[16][64];
    __shared__ float Bs2[(MODE==1)?16:1][(MODE==1)?64:1];

    int tid = threadIdx.x;
    int tx = tid & 15, ty = tid >> 4;

    float acc1[4][4] = {};
    float acc2[4][4] = {};

    int arow_l = tid >> 2;              // 0..63
    int akq    = (tid & 3) << 2;        // 0,4,8,12
    int grow   = mblk * 64 + arow_l;
    bool avalid = grow < M;
    int asrc = 0;
    if (avalid) asrc = (MODE == 1) ? rowidx[grow] : grow;

    int brow = tid >> 4;                // 0..15
    int bcol = (tid & 15) << 2;         // 0..60

    const float* Aptr  = A  + (size_t)asrc * K + akq;
    const float* B1ptr = B1 + (size_t)brow * Ncols + (size_t)nblk * 64 + bcol;
    const float* B2ptr = B1ptr;
    if (MODE == 1) B2ptr = B2 + (size_t)brow * Ncols + (size_t)nblk * 64 + bcol;

    for (int k0 = 0; k0 < K; k0 += 16) {
        float4 av = make_float4(0.f, 0.f, 0.f, 0.f);
        if (avalid) av = *(const float4*)(Aptr + k0);
        float4 bv1 = *(const float4*)(B1ptr + (size_t)k0 * Ncols);
        float4 bv2 = make_float4(0.f, 0.f, 0.f, 0.f);
        if (MODE == 1) bv2 = *(const float4*)(B2ptr + (size_t)k0 * Ncols);

        __syncthreads();
        As[akq + 0][arow_l] = av.x;
        As[akq + 1][arow_l] = av.y;
        As[akq + 2][arow_l] = av.z;
        As[akq + 3][arow_l] = av.w;
        *(float4*)&Bs1[brow][bcol] = bv1;
        if (MODE == 1) *(float4*)&Bs2[brow][bcol] = bv2;
        __syncthreads();

#pragma unroll
        for (int k = 0; k < 16; k++) {
            float4 ra  = *(const float4*)&As[k][ty << 2];
            float4 rb1 = *(const float4*)&Bs1[k][tx << 2];
            float aa[4] = {ra.x, ra.y, ra.z, ra.w};
            float bb[4] = {rb1.x, rb1.y, rb1.z, rb1.w};
#pragma unroll
            for (int i = 0; i < 4; i++)
#pragma unroll
                for (int j = 0; j < 4; j++)
                    acc1[i][j] = fmaf(aa[i], bb[j], acc1[i][j]);
            if (MODE == 1) {
                float4 rb2 = *(const float4*)&Bs2[k][tx << 2];
                float b2[4] = {rb2.x, rb2.y, rb2.z, rb2.w};
#pragma unroll
                for (int i = 0; i < 4; i++)
#pragma unroll
                    for (int j = 0; j < 4; j++)
                        acc2[i][j] = fmaf(aa[i], b2[j], acc2[i][j]);
            }
        }
    }

#pragma unroll
    for (int i = 0; i < 4; i++) {
        int gr = mblk * 64 + (ty << 2) + i;
        if (gr >= M) continue;
        int outrow = gr;
        if (MODE == 2) outrow = rowidx[gr];
#pragma unroll
        for (int j = 0; j < 4; j++) {
            int gc = nblk * 64 + (tx << 2) + j;
            float v = acc1[i][j];
            if (MODE == 0) {
                C1[(size_t)gr * Ncols + gc] = softplusf(v + bias[gc]);
            } else if (MODE == 1) {
                C1[(size_t)gr * Ncols + gc] = v;
                C2[(size_t)gr * Ncols + gc] = acc2[i][j];
            } else {
                C1[(size_t)outrow * Ncols + gc] += v;
            }
        }
    }
}

// ---------------- small projections: Bm, Cm (from x) ----------------
__global__ __launch_bounds__(128)
void proj_small(const float* __restrict__ x, const float* __restrict__ WB,
                const float* __restrict__ WC)
{
    int n = blockIdx.x;
    __shared__ float xs[DD];
    const float* xr = x + (size_t)n * DD;
    for (int i = threadIdx.x; i < DD; i += 128) xs[i] = xr[i];
    __syncthreads();
    int warp = threadIdx.x >> 5, lane = threadIdx.x & 31;
    for (int c = warp; c < 32; c += 4) {
        const float* W; int col; float* out;
        if (c < 16) { W = WB; col = c;      out = g_Bm + (size_t)n * SS + col; }
        else        { W = WC; col = c - 16; out = g_Cm + (size_t)n * SS + col; }
        float s = 0.f;
        for (int k = lane; k < DD; k += 32)
            s = fmaf(xs[k], W[(size_t)k * SS + col], s);
        s += __shfl_xor_sync(~0u, s, 16);
        s += __shfl_xor_sync(~0u, s, 8);
        s += __shfl_xor_sync(~0u, s, 4);
        s += __shfl_xor_sync(~0u, s, 2);
        s += __shfl_xor_sync(~0u, s, 1);
        if (lane == 0) *out = s;
    }
}

// ---------------- selective scan ----------------
// one thread per (b, d, s); block = 16 d x 16 s; grid = B * D/16 = 128
__global__ __launch_bounds__(256)
void scan_kernel(const float* __restrict__ x, const float* __restrict__ A_log,
                 const float* __restrict__ D_param)
{
    int b = blockIdx.x >> 6;
    int dchunk = blockIdx.x & 63;
    int dl = threadIdx.x >> 4;      // d-local 0..15
    int s  = threadIdx.x & 15;      // state index
    int d = dchunk * 16 + dl;

    float A_ds = -__expf(A_log[d * SS + s]);
    float Dp = D_param[d];

    __shared__ float sx[16][16], sd[16][16];
    __shared__ float sB[16][17], sC[16][17], sy[16][17];

    int tt = threadIdx.x >> 4;
    int cc = threadIdx.x & 15;
    const int base_bt = b * LL;

    // prologue: stage tile 0 into registers
    size_t xoff = ((size_t)(base_bt + tt)) * DD + dchunk * 16 + cc;
    float rx = x[xoff];
    float rd = g_delta[xoff];
    size_t boff = ((size_t)(base_bt + tt)) * SS + cc;
    float rB = g_Bm[boff];
    float rC = g_Cm[boff];

    float h = 0.f;
    for (int t0 = 0; t0 < LL; t0 += 16) {
        __syncthreads();
        sx[tt][cc] = rx; sd[tt][cc] = rd; sB[tt][cc] = rB; sC[tt][cc] = rC;
        __syncthreads();
        if (t0 + 16 < LL) {   // prefetch next tile
            size_t xo = ((size_t)(base_bt + t0 + 16 + tt)) * DD + dchunk * 16 + cc;
            rx = x[xo]; rd = g_delta[xo];
            size_t bo = ((size_t)(base_bt + t0 + 16 + tt)) * SS + cc;
            rB = g_Bm[bo]; rC = g_Cm[bo];
        }
#pragma unroll
        for (int q = 0; q < 16; q++) {
            float xv = sx[q][dl], dv = sd[q][dl];
            float Bv = sB[q][s],  Cv = sC[q][s];
            float a  = __expf(fminf(dv * A_ds, 10.f));
            float bB = fminf(fmaxf(dv * Bv, -10.f), 10.f);
            h = fminf(fmaxf(a * h + bB * xv, -10000.f), 10000.f);
            float p = h * Cv;
            p += __shfl_xor_sync(~0u, p, 8);
            p += __shfl_xor_sync(~0u, p, 4);
            p += __shfl_xor_sync(~0u, p, 2);
            p += __shfl_xor_sync(~0u, p, 1);
            if (s == 0) sy[q][dl] = fmaf(xv, Dp, p);
        }
        __syncthreads();
        size_t yo = ((size_t)(base_bt + t0 + tt)) * DD + dchunk * 16 + cc;
        float yv = sy[tt][cc];
        g_ssm[yo] = yv;
        g_acc[yo] = yv;   // residual base for MoE accumulation
    }
}

// ---------------- router: logits from SSM OUTPUT, softmax, top-2, lists --------
__global__ __launch_bounds__(128)
void router_kernel(const float* __restrict__ WR)
{
    int n = blockIdx.x;
    __shared__ float xs[DD];
    __shared__ float logits[EE];
    const float* xr = g_ssm + (size_t)n * DD;
    for (int i = threadIdx.x; i < DD; i += 128) xs[i] = xr[i];
    __syncthreads();
    int warp = threadIdx.x >> 5, lane = threadIdx.x & 31;
    // warp e computes logit e
    {
        float s = 0.f;
        for (int k = lane; k < DD; k += 32)
            s = fmaf(xs[k], WR[(size_t)k * EE + warp], s);
        s += __shfl_xor_sync(~0u, s, 16);
        s += __shfl_xor_sync(~0u, s, 8);
        s += __shfl_xor_sync(~0u, s, 4);
        s += __shfl_xor_sync(~0u, s, 2);
        s += __shfl_xor_sync(~0u, s, 1);
        if (lane == 0) logits[warp] = s;
    }
    __syncthreads();
    if (threadIdx.x == 0) {
        float l[4] = {logits[0], logits[1], logits[2], logits[3]};
        float m = fmaxf(fmaxf(l[0], l[1]), fmaxf(l[2], l[3]));
        float e[4], sum = 0.f;
#pragma unroll
        for (int i = 0; i < 4; i++) { e[i] = __expf(l[i] - m); sum += e[i]; }
        float p[4];
#pragma unroll
        for (int i = 0; i < 4; i++) p[i] = e[i] / sum;
        int i0 = 0;
#pragma unroll
        for (int i = 1; i < 4; i++) if (p[i] > p[i0]) i0 = i;
        int i1 = -1;
#pragma unroll
        for (int i = 0; i < 4; i++) {
            if (i == i0) continue;
            if (i1 < 0 || p[i] > p[i1]) i1 = i;
        }
        float w0 = p[i0], w1 = p[i1];
        float sw = w0 + w1 + 1e-9f;
        w0 /= sw; w1 /= sw;
        int pos = atomicAdd(&g_cnt[i0], 1);
        g_list[i0*NN + pos] = n; g_cw[i0*NN + pos] = w0;
        pos = atomicAdd(&g_cnt[i1], 1);
        g_list[i1*NN + pos] = n; g_cw[i1*NN + pos] = w1;
    }
}

// ---------------- silu(G)*U -> rmsnorm(wn) -> * combine weight ----------------
__global__ __launch_bounds__(256)
void act_norm(const float* __restrict__ wn, const float* __restrict__ cw,
              const int* __restrict__ cntp)
{
    int i = blockIdx.x;
    if (i >= *cntp) return;
    __shared__ float buf[HH];
    __shared__ float red[8];
    float ss = 0.f;
    for (int j = threadIdx.x; j < HH; j += 256) {
        float g = g_G[(size_t)i * HH + j];
        float u = g_U[(size_t)i * HH + j];
        float v = (g / (1.f + __expf(-g))) * u;
        buf[j] = v;
        ss = fmaf(v, v, ss);
    }
    ss += __shfl_xor_sync(~0u, ss, 16);
    ss += __shfl_xor_sync(~0u, ss, 8);
    ss += __shfl_xor_sync(~0u, ss, 4);
    ss += __shfl_xor_sync(~0u, ss, 2);
    ss += __shfl_xor_sync(~0u, ss, 1);
    if ((threadIdx.x & 31) == 0) red[threadIdx.x >> 5] = ss;
    __syncthreads();
    if (threadIdx.x < 32) {
        float v = (threadIdx.x < 8) ? red[threadIdx.x] : 0.f;
        v += __shfl_xor_sync(~0u, v, 4);
        v += __shfl_xor_sync(~0u, v, 2);
        v += __shfl_xor_sync(~0u, v, 1);
        if (threadIdx.x == 0) red[0] = v;
    }
    __syncthreads();
    float scale = cw[i] * rsqrtf(red[0] / (float)HH + 1e-6f);
    for (int j = threadIdx.x; j < HH; j += 256)
        g_act[(size_t)i * HH + j] = wn[j] * buf[j] * scale;
}

// ---------------- final rmsnorm over (ssm + moe) ----------------
__global__ __launch_bounds__(256)
void final_norm(const float* __restrict__ norm_w, float* __restrict__ out)
{
    int n = blockIdx.x;
    __shared__ float red[8];
    float ss = 0.f;
    const float* row = g_acc + (size_t)n * DD;
    for (int j = threadIdx.x; j < DD; j += 256) {
        float v = row[j];
        ss = fmaf(v, v, ss);
    }
    ss += __shfl_xor_sync(~0u, ss, 16);
    ss += __shfl_xor_sync(~0u, ss, 8);
    ss += __shfl_xor_sync(~0u, ss, 4);
    ss += __shfl_xor_sync(~0u, ss, 2);
    ss += __shfl_xor_sync(~0u, ss, 1);
    if ((threadIdx.x & 31) == 0) red[threadIdx.x >> 5] = ss;
    __syncthreads();
    if (threadIdx.x < 32) {
        float v = (threadIdx.x < 8) ? red[threadIdx.x] : 0.f;
        v += __shfl_xor_sync(~0u, v, 4);
        v += __shfl_xor_sync(~0u, v, 2);
        v += __shfl_xor_sync(~0u, v, 1);
        if (threadIdx.x == 0) red[0] = v;
    }
    __syncthreads();
    float inv = rsqrtf(red[0] / (float)DD + 1e-6f);
    for (int j = threadIdx.x; j < DD; j += 256)
        out[(size_t)n * DD + j] = norm_w[j] * row[j] * inv;
}

// ---------------- launch ----------------
extern "C" void kernel_launch(void* const* d_in, const int* in_sizes, int n_in,
                              void* d_out, int out_size)
{
    const float* x        = (const float*)d_in[0];
    const float* A_log    = (const float*)d_in[1];
    const float* D_param  = (const float*)d_in[2];
    const float* W_delta  = (const float*)d_in[3];
    const float* b_delta  = (const float*)d_in[4];
    const float* W_B      = (const float*)d_in[5];
    const float* W_C      = (const float*)d_in[6];
    const float* W_router = (const float*)d_in[7];
    const float* Wg       = (const float*)d_in[8];
    const float* Wu       = (const float*)d_in[9];
    const float* Wd       = (const float*)d_in[10];
    const float* wn_exp   = (const float*)d_in[11];
    const float* norm_w   = (const float*)d_in[12];
    float* out = (float*)d_out;

    float *p_delta, *p_G, *p_U, *p_act, *p_ssm, *p_acc, *p_cw;
    int *p_cnt, *p_list;
    cudaGetSymbolAddress((void**)&p_delta, g_delta);
    cudaGetSymbolAddress((void**)&p_G,     g_G);
    cudaGetSymbolAddress((void**)&p_U,     g_U);
    cudaGetSymbolAddress((void**)&p_act,   g_act);
    cudaGetSymbolAddress((void**)&p_ssm,   g_ssm);
    cudaGetSymbolAddress((void**)&p_acc,   g_acc);
    cudaGetSymbolAddress((void**)&p_cnt,   g_cnt);
    cudaGetSymbolAddress((void**)&p_list,  g_list);
    cudaGetSymbolAddress((void**)&p_cw,    g_cw);

    zero_counts<<<1, 32>>>();

    // delta = softplus(x @ W_delta + b)
    {
        dim3 grid(DD / 64, NN / 64);
        gemm64<0><<<grid, 256>>>(x, W_delta, nullptr, p_delta, nullptr, b_delta,
                                 NN, DD, DD, nullptr, nullptr);
    }

    // Bm, Cm from x
    proj_small<<<NN, 128>>>(x, W_B, W_C);

    // selective scan -> g_ssm (and g_acc residual copy)
    scan_kernel<<<BB * (DD / 16), 256>>>(x, A_log, D_param);

    // router on SSM OUTPUT: softmax / top-2 / expert token lists
    router_kernel<<<NN, 128>>>(W_router);

    // experts
    for (int e = 0; e < EE; e++) {
        const float* Wg_e = Wg + (size_t)e * DD * HH;
        const float* Wu_e = Wu + (size_t)e * DD * HH;
        const float* Wd_e = Wd + (size_t)e * HH * DD;
        const float* wn_e = wn_exp + (size_t)e * HH;
        const int* rowidx = p_list + (size_t)e * NN;
        const int* cntp   = p_cnt + e;
        const float* cwp  = p_cw + (size_t)e * NN;

        // G = gather(ssm) @ Wg_e ; U = gather(ssm) @ Wu_e
        {
            dim3 grid(HH / 64, NN / 64);
            gemm64<1><<<grid, 256>>>(p_ssm, Wg_e, Wu_e, p_G, p_U, nullptr,
                                     0, HH, DD, rowidx, cntp);
        }
        // act = wn * rmsnorm(silu(G)*U) * cw
        act_norm<<<NN, 256>>>(wn_e, cwp, cntp);
        // acc[token] += act @ Wd_e
        {
            dim3 grid(DD / 64, NN / 64);
            gemm64<2><<<grid, 256>>>(p_act, Wd_e, nullptr, p_acc, nullptr, nullptr,
                                     0, DD, HH, rowidx, cntp);
        }
    }

    // out = rmsnorm(ssm + moe, norm_w)
    final_norm<<<NN, 256>>>(norm_w, out);
}

// round 5
// speedup vs baseline: 1.9704x; 1.9704x over previous
#include <cuda_runtime.h>
#include <cuda_bf16.h>
#include <math.h>
#include <stdint.h>

// Problem dims (fixed)
#define BB 2
#define LL 2048
#define DD 1024
#define SS 16
#define EE 4
#define HH 2048
#define NN (BB*LL)   // 4096

typedef uint32_t u32;

// ---------------- scratch (device globals; no allocation allowed) ----------------
__device__ float g_delta[NN*DD];
__device__ float g_Bm[NN*SS];
__device__ float g_Cm[NN*SS];
__device__ float g_ssm[NN*DD];
__device__ float g_acc[NN*DD];
__device__ int   g_cnt[EE];
__device__ int   g_list[EE*NN];
__device__ float g_cw[EE*NN];
__device__ float g_G[NN*HH];
__device__ float g_U[NN*HH];

// bf16x2 split operand arrays (packed: low16 = even k, high16 = odd k)
__device__ u32 g_xHi[NN*DD/2],   g_xLo[NN*DD/2];      // x           [NN][512]
__device__ u32 g_sHi[NN*DD/2],   g_sLo[NN*DD/2];      // ssm         [NN][512]
__device__ u32 g_aHi[NN*HH/2],   g_aLo[NN*HH/2];      // act         [NN][1024]
__device__ u32 g_WdHi[DD*DD/2],  g_WdLo[DD*DD/2];     // W_delta^T   [D][512]
__device__ u32 g_WgHi[EE*HH*DD/2], g_WgLo[EE*HH*DD/2];// Wg^T        [e][H][512]
__device__ u32 g_WuHi[EE*HH*DD/2], g_WuLo[EE*HH*DD/2];// Wu^T        [e][H][512]
__device__ u32 g_WnHi[EE*DD*HH/2], g_WnLo[EE*DD*HH/2];// Wd^T        [e][D][1024]

__device__ __forceinline__ float softplusf(float z) {
    return (z > 20.f) ? z : log1pf(__expf(z));
}

__device__ __forceinline__ void split2(float a, float b, u32& hi, u32& lo) {
    __nv_bfloat16 ah = __float2bfloat16(a);
    __nv_bfloat16 bh = __float2bfloat16(b);
    float ra = a - __bfloat162float(ah);
    float rb = b - __bfloat162float(bh);
    __nv_bfloat16 al = __float2bfloat16(ra);
    __nv_bfloat16 bl = __float2bfloat16(rb);
    hi = ((u32)__bfloat16_as_ushort(bh) << 16) | __bfloat16_as_ushort(ah);
    lo = ((u32)__bfloat16_as_ushort(bl) << 16) | __bfloat16_as_ushort(al);
}

// ---------------- zero counts ----------------
__global__ void zero_counts() {
    if (threadIdx.x < EE) g_cnt[threadIdx.x] = 0;
}

// ---------------- split x (row-major, k-contiguous) ----------------
__global__ __launch_bounds__(256)
void split_x_kernel(const float* __restrict__ in, u32* __restrict__ oh,
                    u32* __restrict__ ol, int n2) {
    int i = blockIdx.x * blockDim.x + threadIdx.x;
    if (i < n2) {
        float2 v = ((const float2*)in)[i];
        u32 hi, lo; split2(v.x, v.y, hi, lo);
        oh[i] = hi; ol[i] = lo;
    }
}

// ---------------- split + transpose weights: W[K][N] -> out[n][kp] -------------
// grid: (K2/32, N/32, E); block (32, 8)
__global__ __launch_bounds__(256)
void split_w_kernel(const float* __restrict__ W, u32* __restrict__ oh,
                    u32* __restrict__ ol, int K, int N) {
    int K2 = K / 2;
    size_t eoffW = (size_t)blockIdx.z * K * N;
    size_t eoffO = (size_t)blockIdx.z * N * K2;
    __shared__ u32 th[32][33], tl[32][33];
    int kp0 = blockIdx.x * 32, n0 = blockIdx.y * 32;
    int tx = threadIdx.x, ty = threadIdx.y;
#pragma unroll
    for (int r = 0; r < 4; r++) {
        int kp = kp0 + ty + r * 8;
        int n  = n0 + tx;
        float w0 = W[eoffW + (size_t)(2 * kp) * N + n];
        float w1 = W[eoffW + (size_t)(2 * kp + 1) * N + n];
        u32 hi, lo; split2(w0, w1, hi, lo);
        th[ty + r * 8][tx] = hi;
        tl[ty + r * 8][tx] = lo;
    }
    __syncthreads();
#pragma unroll
    for (int r = 0; r < 4; r++) {
        int n  = n0 + ty + r * 8;
        int kp = kp0 + tx;
        oh[eoffO + (size_t)n * K2 + kp] = th[tx][ty + r * 8];
        ol[eoffO + (size_t)n * K2 + kp] = tl[tx][ty + r * 8];
    }
}

// ---------------- cp.async helpers ----------------
__device__ __forceinline__ void cp_async16z(void* dst, const void* src, int sz) {
    u32 d = (u32)__cvta_generic_to_shared(dst);
    asm volatile("cp.async.ca.shared.global [%0], [%1], 16, %2;\n"
                 :: "r"(d), "l"(src), "r"(sz) : "memory");
}
__device__ __forceinline__ void cp_commit() {
    asm volatile("cp.async.commit_group;\n" ::: "memory");
}
template<int N> __device__ __forceinline__ void cp_wait() {
    asm volatile("cp.async.wait_group %0;\n" :: "n"(N) : "memory");
}

// ---------------- bf16 m16n8k16 mma ----------------
__device__ __forceinline__ void mma_bf16(float* d, const u32* a, const u32* b) {
    asm volatile(
        "mma.sync.aligned.m16n8k16.row.col.f32.bf16.bf16.f32 "
        "{%0,%1,%2,%3}, {%4,%5,%6,%7}, {%8,%9}, {%0,%1,%2,%3};\n"
        : "+f"(d[0]), "+f"(d[1]), "+f"(d[2]), "+f"(d[3])
        : "r"(a[0]), "r"(a[1]), "r"(a[2]), "r"(a[3]), "r"(b[0]), "r"(b[1]));
}

// ---------------- bf16x2 split tensor-core GEMM: 128x128x32 tiles --------------
// Operands are packed bf16-pair arrays: A [row][K/2], B [n][K/2] (pre-transposed).
// MODE 0: C1[r,:] = softplus(acc + bias), direct rows (delta projection)
// MODE 1: rows gathered via rowidx, M=*cntp; nblk<16 -> B1/C1 (G), else B2/C2 (U)
// MODE 2: compact A rows; C1[rowidx[r],:] += acc (down projection scatter)
#define BM 128
#define BN 128
#define KP 16            // k-pairs per tile (32 elements)
#define STR 20           // smem row stride in u32 (16 used + 4 pad)
#define ABUF (128*STR)   // 2560 u32 per array per buffer
#define GEMM_SMEM_BYTES (8*ABUF*4 + BM*4)

template<int MODE>
__global__ __launch_bounds__(256, 1)
void gemm_bf(const u32* __restrict__ Ahi, const u32* __restrict__ Alo,
             const u32* __restrict__ B1hi, const u32* __restrict__ B1lo,
             const u32* __restrict__ B2hi, const u32* __restrict__ B2lo,
             float* __restrict__ C1, float* __restrict__ C2,
             const float* __restrict__ bias,
             int M, int Ncols, int K,
             const int* __restrict__ rowidx, const int* __restrict__ cntp)
{
    extern __shared__ u32 sm[];
    int* sidx = (int*)(sm + 8 * ABUF);

    if (MODE != 0) M = *cntp;
    int mblk = blockIdx.y;
    if (mblk * BM >= M) return;
    int nblk = blockIdx.x;

    const u32* Bhi = B1hi;
    const u32* Blo = B1lo;
    float* Cout = C1;
    int nb = nblk;
    if (MODE == 1 && nblk >= 16) { Bhi = B2hi; Blo = B2lo; Cout = C2; nb = nblk - 16; }
    int n0 = nb * BN;
    int K2 = K / 2;

    int tid = threadIdx.x;

    if (MODE >= 1) {
        for (int i = tid; i < BM; i += 256) {
            int gr = mblk * BM + i;
            sidx[i] = (gr < M) ? rowidx[gr] : -1;
        }
        __syncthreads();
    }

    // gmem->smem mapping: each thread copies half a row (8 u32) of each array
    int crow = tid >> 1;
    int cseg = (tid & 1) * 8;
    int asz;
    size_t abase;
    if (MODE == 1) {
        int s = sidx[crow];
        asz = (s >= 0) ? 16 : 0;
        abase = (size_t)(s >= 0 ? s : 0) * K2 + cseg;
    } else {
        int gr = mblk * BM + crow;
        asz = (gr < M) ? 16 : 0;
        abase = (size_t)(gr < M ? gr : 0) * K2 + cseg;
    }
    size_t bbase = (size_t)(n0 + crow) * K2 + cseg;

    // warp fragment mapping
    int wid = tid >> 5, lane = tid & 31;
    int g = lane >> 2, tig = lane & 3;
    int wm = wid >> 2, wn = wid & 3;   // 2 x 4 warps, each 64x32 output

    float acc[4][4][4];
#pragma unroll
    for (int i = 0; i < 4; i++)
#pragma unroll
        for (int j = 0; j < 4; j++)
#pragma unroll
            for (int k = 0; k < 4; k++) acc[i][j][k] = 0.f;

    int KT = K2 / KP;
    int buf = 0;
    u32 sdst = crow * STR + cseg;

    // stage tile 0
    {
        u32* s0 = sm + 0 * 4 * ABUF;
        cp_async16z(s0 + 0*ABUF + sdst,     Ahi + abase,     asz);
        cp_async16z(s0 + 0*ABUF + sdst + 4, Ahi + abase + 4, asz);
        cp_async16z(s0 + 1*ABUF + sdst,     Alo + abase,     asz);
        cp_async16z(s0 + 1*ABUF + sdst + 4, Alo + abase + 4, asz);
        cp_async16z(s0 + 2*ABUF + sdst,     Bhi + bbase,     16);
        cp_async16z(s0 + 2*ABUF + sdst + 4, Bhi + bbase + 4, 16);
        cp_async16z(s0 + 3*ABUF + sdst,     Blo + bbase,     16);
        cp_async16z(s0 + 3*ABUF + sdst + 4, Blo + bbase + 4, 16);
        cp_commit();
    }

    for (int kt = 0; kt < KT; kt++) {
        if (kt + 1 < KT) {
            u32* s1 = sm + (buf ^ 1) * 4 * ABUF;
            size_t ao = abase + (size_t)(kt + 1) * KP;
            size_t bo = bbase + (size_t)(kt + 1) * KP;
            cp_async16z(s1 + 0*ABUF + sdst,     Ahi + ao,     asz);
            cp_async16z(s1 + 0*ABUF + sdst + 4, Ahi + ao + 4, asz);
            cp_async16z(s1 + 1*ABUF + sdst,     Alo + ao,     asz);
            cp_async16z(s1 + 1*ABUF + sdst + 4, Alo + ao + 4, asz);
            cp_async16z(s1 + 2*ABUF + sdst,     Bhi + bo,     16);
            cp_async16z(s1 + 2*ABUF + sdst + 4, Bhi + bo + 4, 16);
            cp_async16z(s1 + 3*ABUF + sdst,     Blo + bo,     16);
            cp_async16z(s1 + 3*ABUF + sdst + 4, Blo + bo + 4, 16);
            cp_commit();
            cp_wait<1>();
        } else {
            cp_wait<0>();
        }
        __syncthreads();

        const u32* sAh = sm + buf * 4 * ABUF + 0 * ABUF;
        const u32* sAl = sAh + ABUF;
        const u32* sBh = sAh + 2 * ABUF;
        const u32* sBl = sAh + 3 * ABUF;

#pragma unroll
        for (int ks = 0; ks < 2; ks++) {
            int kb = ks * 8;
            u32 ah[4][4], al[4][4];
#pragma unroll
            for (int mt = 0; mt < 4; mt++) {
                int row = wm * 64 + mt * 16 + g;
                ah[mt][0] = sAh[row * STR + kb + tig];
                ah[mt][1] = sAh[(row + 8) * STR + kb + tig];
                ah[mt][2] = sAh[row * STR + kb + tig + 4];
                ah[mt][3] = sAh[(row + 8) * STR + kb + tig + 4];
                al[mt][0] = sAl[row * STR + kb + tig];
                al[mt][1] = sAl[(row + 8) * STR + kb + tig];
                al[mt][2] = sAl[row * STR + kb + tig + 4];
                al[mt][3] = sAl[(row + 8) * STR + kb + tig + 4];
            }
            u32 bh[4][2], bl[4][2];
#pragma unroll
            for (int nt = 0; nt < 4; nt++) {
                int col = wn * 32 + nt * 8 + g;
                bh[nt][0] = sBh[col * STR + kb + tig];
                bh[nt][1] = sBh[col * STR + kb + tig + 4];
                bl[nt][0] = sBl[col * STR + kb + tig];
                bl[nt][1] = sBl[col * STR + kb + tig + 4];
            }
#pragma unroll
            for (int mt = 0; mt < 4; mt++)
#pragma unroll
                for (int nt = 0; nt < 4; nt++) {
                    mma_bf16(acc[mt][nt], ah[mt], bh[nt]);
                    mma_bf16(acc[mt][nt], ah[mt], bl[nt]);
                    mma_bf16(acc[mt][nt], al[mt], bh[nt]);
                }
        }
        __syncthreads();
        buf ^= 1;
    }

    // epilogue
#pragma unroll
    for (int mt = 0; mt < 4; mt++) {
#pragma unroll
        for (int half = 0; half < 2; half++) {
            int lr = wm * 64 + mt * 16 + g + half * 8;
            int gr = mblk * BM + lr;
            if (gr >= M) continue;
            float* orow;
            if (MODE == 2) {
                int tok = sidx[lr];
                orow = C1 + (size_t)tok * Ncols;
            } else {
                orow = Cout + (size_t)gr * Ncols;
            }
#pragma unroll
            for (int nt = 0; nt < 4; nt++) {
                int col = n0 + wn * 32 + nt * 8 + tig * 2;
                float v0 = acc[mt][nt][half * 2 + 0];
                float v1 = acc[mt][nt][half * 2 + 1];
                if (MODE == 0) {
                    v0 = softplusf(v0 + bias[col]);
                    v1 = softplusf(v1 + bias[col + 1]);
                    *(float2*)(orow + col) = make_float2(v0, v1);
                } else if (MODE == 1) {
                    *(float2*)(orow + col) = make_float2(v0, v1);
                } else {
                    float2 old = *(float2*)(orow + col);
                    old.x += v0; old.y += v1;
                    *(float2*)(orow + col) = old;
                }
            }
        }
    }
}

// ---------------- small projections: Bm, Cm (from x) ----------------
__global__ __launch_bounds__(128)
void proj_small(const float* __restrict__ x, const float* __restrict__ WB,
                const float* __restrict__ WC)
{
    int n = blockIdx.x;
    __shared__ float xs[DD];
    const float* xr = x + (size_t)n * DD;
    for (int i = threadIdx.x; i < DD; i += 128) xs[i] = xr[i];
    __syncthreads();
    int warp = threadIdx.x >> 5, lane = threadIdx.x & 31;
    for (int c = warp; c < 32; c += 4) {
        const float* W; int col; float* out;
        if (c < 16) { W = WB; col = c;      out = g_Bm + (size_t)n * SS + col; }
        else        { W = WC; col = c - 16; out = g_Cm + (size_t)n * SS + col; }
        float s = 0.f;
        for (int k = lane; k < DD; k += 32)
            s = fmaf(xs[k], W[(size_t)k * SS + col], s);
        s += __shfl_xor_sync(~0u, s, 16);
        s += __shfl_xor_sync(~0u, s, 8);
        s += __shfl_xor_sync(~0u, s, 4);
        s += __shfl_xor_sync(~0u, s, 2);
        s += __shfl_xor_sync(~0u, s, 1);
        if (lane == 0) *out = s;
    }
}

// ---------------- selective scan (+ split write of ssm) ----------------
__global__ __launch_bounds__(256)
void scan_kernel(const float* __restrict__ x, const float* __restrict__ A_log,
                 const float* __restrict__ D_param)
{
    int b = blockIdx.x >> 6;
    int dchunk = blockIdx.x & 63;
    int dl = threadIdx.x >> 4;
    int s  = threadIdx.x & 15;
    int d = dchunk * 16 + dl;

    float A_ds = -__expf(A_log[d * SS + s]);
    float Dp = D_param[d];

    __shared__ float sx[16][16], sd[16][16];
    __shared__ float sB[16][17], sC[16][17], sy[16][17];

    int tt = threadIdx.x >> 4;
    int cc = threadIdx.x & 15;
    const int base_bt = b * LL;

    size_t xoff = ((size_t)(base_bt + tt)) * DD + dchunk * 16 + cc;
    float rx = x[xoff];
    float rd = g_delta[xoff];
    size_t boff = ((size_t)(base_bt + tt)) * SS + cc;
    float rB = g_Bm[boff];
    float rC = g_Cm[boff];

    float h = 0.f;
    for (int t0 = 0; t0 < LL; t0 += 16) {
        __syncthreads();
        sx[tt][cc] = rx; sd[tt][cc] = rd; sB[tt][cc] = rB; sC[tt][cc] = rC;
        __syncthreads();
        if (t0 + 16 < LL) {
            size_t xo = ((size_t)(base_bt + t0 + 16 + tt)) * DD + dchunk * 16 + cc;
            rx = x[xo]; rd = g_delta[xo];
            size_t bo = ((size_t)(base_bt + t0 + 16 + tt)) * SS + cc;
            rB = g_Bm[bo]; rC = g_Cm[bo];
        }
#pragma unroll
        for (int q = 0; q < 16; q++) {
            float xv = sx[q][dl], dv = sd[q][dl];
            float Bv = sB[q][s],  Cv = sC[q][s];
            float a  = __expf(fminf(dv * A_ds, 10.f));
            float bBc = fminf(fmaxf(dv * Bv, -10.f), 10.f);
            h = fminf(fmaxf(a * h + bBc * xv, -10000.f), 10000.f);
            float p = h * Cv;
            p += __shfl_xor_sync(~0u, p, 8);
            p += __shfl_xor_sync(~0u, p, 4);
            p += __shfl_xor_sync(~0u, p, 2);
            p += __shfl_xor_sync(~0u, p, 1);
            if (s == 0) sy[q][dl] = fmaf(xv, Dp, p);
        }
        __syncthreads();
        size_t yo = ((size_t)(base_bt + t0 + tt)) * DD + dchunk * 16 + cc;
        float yv = sy[tt][cc];
        g_ssm[yo] = yv;
        g_acc[yo] = yv;
        if (cc < 8) {
            float y0 = sy[tt][2 * cc];
            float y1 = sy[tt][2 * cc + 1];
            u32 hi, lo; split2(y0, y1, hi, lo);
            size_t po = ((size_t)(base_bt + t0 + tt)) * (DD/2) + dchunk * 8 + cc;
            g_sHi[po] = hi;
            g_sLo[po] = lo;
        }
    }
}

// ---------------- router on SSM output: softmax, top-2, expert lists ----------
__global__ __launch_bounds__(128)
void router_kernel(const float* __restrict__ WR)
{
    int n = blockIdx.x;
    __shared__ float xs[DD];
    __shared__ float logits[EE];
    const float* xr = g_ssm + (size_t)n * DD;
    for (int i = threadIdx.x; i < DD; i += 128) xs[i] = xr[i];
    __syncthreads();
    int warp = threadIdx.x >> 5, lane = threadIdx.x & 31;
    {
        float s = 0.f;
        for (int k = lane; k < DD; k += 32)
            s = fmaf(xs[k], WR[(size_t)k * EE + warp], s);
        s += __shfl_xor_sync(~0u, s, 16);
        s += __shfl_xor_sync(~0u, s, 8);
        s += __shfl_xor_sync(~0u, s, 4);
        s += __shfl_xor_sync(~0u, s, 2);
        s += __shfl_xor_sync(~0u, s, 1);
        if (lane == 0) logits[warp] = s;
    }
    __syncthreads();
    if (threadIdx.x == 0) {
        float l[4] = {logits[0], logits[1], logits[2], logits[3]};
        float m = fmaxf(fmaxf(l[0], l[1]), fmaxf(l[2], l[3]));
        float e[4], sum = 0.f;
#pragma unroll
        for (int i = 0; i < 4; i++) { e[i] = __expf(l[i] - m); sum += e[i]; }
        float p[4];
#pragma unroll
        for (int i = 0; i < 4; i++) p[i] = e[i] / sum;
        int i0 = 0;
#pragma unroll
        for (int i = 1; i < 4; i++) if (p[i] > p[i0]) i0 = i;
        int i1 = -1;
#pragma unroll
        for (int i = 0; i < 4; i++) {
            if (i == i0) continue;
            if (i1 < 0 || p[i] > p[i1]) i1 = i;
        }
        float w0 = p[i0], w1 = p[i1];
        float sw = w0 + w1 + 1e-9f;
        w0 /= sw; w1 /= sw;
        int pos = atomicAdd(&g_cnt[i0], 1);
        g_list[i0*NN + pos] = n; g_cw[i0*NN + pos] = w0;
        pos = atomicAdd(&g_cnt[i1], 1);
        g_list[i1*NN + pos] = n; g_cw[i1*NN + pos] = w1;
    }
}

// ---------------- silu(G)*U -> rmsnorm(wn) -> * cw (split bf16x2 output) ------
__global__ __launch_bounds__(256)
void act_norm(const float* __restrict__ wn, const float* __restrict__ cw,
              const int* __restrict__ cntp)
{
    int i = blockIdx.x;
    if (i >= *cntp) return;
    __shared__ float buf[HH];
    __shared__ float red[8];
    float ss = 0.f;
    for (int j = threadIdx.x; j < HH; j += 256) {
        float g = g_G[(size_t)i * HH + j];
        float u = g_U[(size_t)i * HH + j];
        float v = (g / (1.f + __expf(-g))) * u;
        buf[j] = v;
        ss = fmaf(v, v, ss);
    }
    ss += __shfl_xor_sync(~0u, ss, 16);
    ss += __shfl_xor_sync(~0u, ss, 8);
    ss += __shfl_xor_sync(~0u, ss, 4);
    ss += __shfl_xor_sync(~0u, ss, 2);
    ss += __shfl_xor_sync(~0u, ss, 1);
    if ((threadIdx.x & 31) == 0) red[threadIdx.x >> 5] = ss;
    __syncthreads();
    if (threadIdx.x < 32) {
        float v = (threadIdx.x < 8) ? red[threadIdx.x] : 0.f;
        v += __shfl_xor_sync(~0u, v, 4);
        v += __shfl_xor_sync(~0u, v, 2);
        v += __shfl_xor_sync(~0u, v, 1);
        if (threadIdx.x == 0) red[0] = v;
    }
    __syncthreads();
    float scale = cw[i] * rsqrtf(red[0] / (float)HH + 1e-6f);
    for (int j2 = threadIdx.x; j2 < HH / 2; j2 += 256) {
        float v0 = wn[2 * j2]     * buf[2 * j2]     * scale;
        float v1 = wn[2 * j2 + 1] * buf[2 * j2 + 1] * scale;
        u32 hi, lo; split2(v0, v1, hi, lo);
        g_aHi[(size_t)i * (HH/2) + j2] = hi;
        g_aLo[(size_t)i * (HH/2) + j2] = lo;
    }
}

// ---------------- final rmsnorm over (ssm + moe) ----------------
__global__ __launch_bounds__(256)
void final_norm(const float* __restrict__ norm_w, float* __restrict__ out)
{
    int n = blockIdx.x;
    __shared__ float red[8];
    float ss = 0.f;
    const float* row = g_acc + (size_t)n * DD;
    for (int j = threadIdx.x; j < DD; j += 256) {
        float v = row[j];
        ss = fmaf(v, v, ss);
    }
    ss += __shfl_xor_sync(~0u, ss, 16);
    ss += __shfl_xor_sync(~0u, ss, 8);
    ss += __shfl_xor_sync(~0u, ss, 4);
    ss += __shfl_xor_sync(~0u, ss, 2);
    ss += __shfl_xor_sync(~0u, ss, 1);
    if ((threadIdx.x & 31) == 0) red[threadIdx.x >> 5] = ss;
    __syncthreads();
    if (threadIdx.x < 32) {
        float v = (threadIdx.x < 8) ? red[threadIdx.x] : 0.f;
        v += __shfl_xor_sync(~0u, v, 4);
        v += __shfl_xor_sync(~0u, v, 2);
        v += __shfl_xor_sync(~0u, v, 1);
        if (threadIdx.x == 0) red[0] = v;
    }
    __syncthreads();
    float inv = rsqrtf(red[0] / (float)DD + 1e-6f);
    for (int j = threadIdx.x; j < DD; j += 256)
        out[(size_t)n * DD + j] = norm_w[j] * row[j] * inv;
}

// ---------------- launch ----------------
extern "C" void kernel_launch(void* const* d_in, const int* in_sizes, int n_in,
                              void* d_out, int out_size)
{
    const float* x        = (const float*)d_in[0];
    const float* A_log    = (const float*)d_in[1];
    const float* D_param  = (const float*)d_in[2];
    const float* W_delta  = (const float*)d_in[3];
    const float* b_delta  = (const float*)d_in[4];
    const float* W_B      = (const float*)d_in[5];
    const float* W_C      = (const float*)d_in[6];
    const float* W_router = (const float*)d_in[7];
    const float* Wg       = (const float*)d_in[8];
    const float* Wu       = (const float*)d_in[9];
    const float* Wd       = (const float*)d_in[10];
    const float* wn_exp   = (const float*)d_in[11];
    const float* norm_w   = (const float*)d_in[12];
    float* out = (float*)d_out;

    float *p_delta, *p_G, *p_U, *p_acc, *p_cw;
    int *p_cnt, *p_list;
    u32 *p_xHi, *p_xLo, *p_sHi, *p_sLo, *p_aHi, *p_aLo;
    u32 *p_WdHi, *p_WdLo, *p_WgHi, *p_WgLo, *p_WuHi, *p_WuLo, *p_WnHi, *p_WnLo;
    cudaGetSymbolAddress((void**)&p_delta, g_delta);
    cudaGetSymbolAddress((void**)&p_G,     g_G);
    cudaGetSymbolAddress((void**)&p_U,     g_U);
    cudaGetSymbolAddress((void**)&p_acc,   g_acc);
    cudaGetSymbolAddress((void**)&p_cnt,   g_cnt);
    cudaGetSymbolAddress((void**)&p_list,  g_list);
    cudaGetSymbolAddress((void**)&p_cw,    g_cw);
    cudaGetSymbolAddress((void**)&p_xHi,   g_xHi);
    cudaGetSymbolAddress((void**)&p_xLo,   g_xLo);
    cudaGetSymbolAddress((void**)&p_sHi,   g_sHi);
    cudaGetSymbolAddress((void**)&p_sLo,   g_sLo);
    cudaGetSymbolAddress((void**)&p_aHi,   g_aHi);
    cudaGetSymbolAddress((void**)&p_aLo,   g_aLo);
    cudaGetSymbolAddress((void**)&p_WdHi,  g_WdHi);
    cudaGetSymbolAddress((void**)&p_WdLo,  g_WdLo);
    cudaGetSymbolAddress((void**)&p_WgHi,  g_WgHi);
    cudaGetSymbolAddress((void**)&p_WgLo,  g_WgLo);
    cudaGetSymbolAddress((void**)&p_WuHi,  g_WuHi);
    cudaGetSymbolAddress((void**)&p_WuLo,  g_WuLo);
    cudaGetSymbolAddress((void**)&p_WnHi,  g_WnHi);
    cudaGetSymbolAddress((void**)&p_WnLo,  g_WnLo);

    cudaFuncSetAttribute(gemm_bf<0>, cudaFuncAttributeMaxDynamicSharedMemorySize, GEMM_SMEM_BYTES);
    cudaFuncSetAttribute(gemm_bf<1>, cudaFuncAttributeMaxDynamicSharedMemorySize, GEMM_SMEM_BYTES);
    cudaFuncSetAttribute(gemm_bf<2>, cudaFuncAttributeMaxDynamicSharedMemorySize, GEMM_SMEM_BYTES);

    zero_counts<<<1, 32>>>();

    // pre-split operands
    {
        int n2 = NN * DD / 2;
        split_x_kernel<<<(n2 + 255) / 256, 256>>>(x, p_xHi, p_xLo, n2);
    }
    {
        dim3 blk(32, 8);
        dim3 gWdel(DD/2/32, DD/32, 1);
        split_w_kernel<<<gWdel, blk>>>(W_delta, p_WdHi, p_WdLo, DD, DD);
        dim3 gUp(DD/2/32, HH/32, EE);
        split_w_kernel<<<gUp, blk>>>(Wg, p_WgHi, p_WgLo, DD, HH);
        split_w_kernel<<<gUp, blk>>>(Wu, p_WuHi, p_WuLo, DD, HH);
        dim3 gDn(HH/2/32, DD/32, EE);
        split_w_kernel<<<gDn, blk>>>(Wd, p_WnHi, p_WnLo, HH, DD);
    }

    // delta = softplus(x @ W_delta + b)   [bf16x2 tensor cores]
    {
        dim3 grid(DD / BN, NN / BM);
        gemm_bf<0><<<grid, 256, GEMM_SMEM_BYTES>>>(
            p_xHi, p_xLo, p_WdHi, p_WdLo, nullptr, nullptr,
            p_delta, nullptr, b_delta, NN, DD, DD, nullptr, nullptr);
    }

    // Bm, Cm from x
    proj_small<<<NN, 128>>>(x, W_B, W_C);

    // selective scan -> g_ssm / g_acc / split ssm
    scan_kernel<<<BB * (DD / 16), 256>>>(x, A_log, D_param);

    // router on SSM output
    router_kernel<<<NN, 128>>>(W_router);

    // experts
    for (int e = 0; e < EE; e++) {
        const u32* WgHi_e = p_WgHi + (size_t)e * HH * (DD/2);
        const u32* WgLo_e = p_WgLo + (size_t)e * HH * (DD/2);
        const u32* WuHi_e = p_WuHi + (size_t)e * HH * (DD/2);
        const u32* WuLo_e = p_WuLo + (size_t)e * HH * (DD/2);
        const u32* WnHi_e = p_WnHi + (size_t)e * DD * (HH/2);
        const u32* WnLo_e = p_WnLo + (size_t)e * DD * (HH/2);
        const float* wn_e = wn_exp + (size_t)e * HH;
        const int* rowidx = p_list + (size_t)e * NN;
        const int* cntp   = p_cnt + e;
        const float* cwp  = p_cw + (size_t)e * NN;

        // G = gather(ssm) @ Wg_e ; U = gather(ssm) @ Wu_e
        {
            dim3 grid(2 * HH / BN, NN / BM);   // nblk<16 -> G, else U
            gemm_bf<1><<<grid, 256, GEMM_SMEM_BYTES>>>(
                p_sHi, p_sLo, WgHi_e, WgLo_e, WuHi_e, WuLo_e,
                p_G, p_U, nullptr, 0, HH, DD, rowidx, cntp);
        }
        // act = wn * rmsnorm(silu(G)*U) * cw  (split output)
        act_norm<<<NN, 256>>>(wn_e, cwp, cntp);
        // acc[token] += act @ Wd_e
        {
            dim3 grid(DD / BN, NN / BM);
            gemm_bf<2><<<grid, 256, GEMM_SMEM_BYTES>>>(
                p_aHi, p_aLo, WnHi_e, WnLo_e, nullptr, nullptr,
                p_acc, nullptr, nullptr, 0, DD, HH, rowidx, cntp);
        }
    }

    // out = rmsnorm(ssm + moe, norm_w)
    final_norm<<<NN, 256>>>(norm_w, out);
}

// round 6
// speedup vs baseline: 2.5263x; 1.2821x over previous
#include <cuda_runtime.h>
#include <cuda_bf16.h>
#include <cuda_fp16.h>
#include <math.h>
#include <stdint.h>

// Problem dims (fixed)
#define BB 2
#define LL 2048
#define DD 1024
#define SS 16
#define EE 4
#define HH 2048
#define NN (BB*LL)   // 4096

typedef uint32_t u32;

// ---------------- scratch (device globals; no allocation allowed) ----------------
__device__ float g_delta[NN*DD];
__device__ float g_Bm[NN*SS];
__device__ float g_Cm[NN*SS];
__device__ float g_ssm[NN*DD];
__device__ float g_acc[NN*DD];
__device__ int   g_cnt[EE];
__device__ int   g_list[EE*NN];
__device__ float g_cw[EE*NN];
__device__ float g_G[NN*HH];
__device__ float g_U[NN*HH];

// bf16x2 split operands for delta GEMM (packed: low16 = even k, high16 = odd k)
__device__ u32 g_xHi[NN*DD/2],   g_xLo[NN*DD/2];      // x           [NN][512]
__device__ u32 g_WdHi[DD*DD/2],  g_WdLo[DD*DD/2];     // W_delta^T   [D][512]
// fp16x2 split A-operands for MoE GEMMs
__device__ u32 g_sHi[NN*DD/2],   g_sLo[NN*DD/2];      // ssm  (fp16 pairs)
__device__ u32 g_aHi[NN*HH/2],   g_aLo[NN*HH/2];      // act  (fp16 pairs)
// fp16 single-precision MoE weights (transposed, pair-packed)
__device__ u32 g_WgF[EE*HH*DD/2];                     // Wg^T  [e][H][512]
__device__ u32 g_WuF[EE*HH*DD/2];                     // Wu^T  [e][H][512]
__device__ u32 g_WnF[EE*DD*HH/2];                     // Wd^T  [e][D][1024]

__device__ __forceinline__ float softplusf(float z) {
    return (z > 20.f) ? z : log1pf(__expf(z));
}

__device__ __forceinline__ void split2(float a, float b, u32& hi, u32& lo) {
    __nv_bfloat16 ah = __float2bfloat16(a);
    __nv_bfloat16 bh = __float2bfloat16(b);
    float ra = a - __bfloat162float(ah);
    float rb = b - __bfloat162float(bh);
    __nv_bfloat16 al = __float2bfloat16(ra);
    __nv_bfloat16 bl = __float2bfloat16(rb);
    hi = ((u32)__bfloat16_as_ushort(bh) << 16) | __bfloat16_as_ushort(ah);
    lo = ((u32)__bfloat16_as_ushort(bl) << 16) | __bfloat16_as_ushort(al);
}

__device__ __forceinline__ u32 pack_h2(float a, float b) {
    __half2 h = __floats2half2_rn(a, b);
    return *reinterpret_cast<u32*>(&h);
}
__device__ __forceinline__ void split2h(float a, float b, u32& hi, u32& lo) {
    __half2 h = __floats2half2_rn(a, b);
    float2 hf = __half22float2(h);
    hi = *reinterpret_cast<u32*>(&h);
    __half2 l = __floats2half2_rn(a - hf.x, b - hf.y);
    lo = *reinterpret_cast<u32*>(&l);
}

// ---------------- zero counts ----------------
__global__ void zero_counts() {
    if (threadIdx.x < EE) g_cnt[threadIdx.x] = 0;
}

// ---------------- split x (bf16 pairs, row-major) ----------------
__global__ __launch_bounds__(256)
void split_x_kernel(const float* __restrict__ in, u32* __restrict__ oh,
                    u32* __restrict__ ol, int n2) {
    int i = blockIdx.x * blockDim.x + threadIdx.x;
    if (i < n2) {
        float2 v = ((const float2*)in)[i];
        u32 hi, lo; split2(v.x, v.y, hi, lo);
        oh[i] = hi; ol[i] = lo;
    }
}

// ---------------- split + transpose W_delta (bf16 pairs) ----------------
__global__ __launch_bounds__(256)
void split_w_kernel(const float* __restrict__ W, u32* __restrict__ oh,
                    u32* __restrict__ ol, int K, int N) {
    int K2 = K / 2;
    __shared__ u32 th[32][33], tl[32][33];
    int kp0 = blockIdx.x * 32, n0 = blockIdx.y * 32;
    int tx = threadIdx.x, ty = threadIdx.y;
#pragma unroll
    for (int r = 0; r < 4; r++) {
        int kp = kp0 + ty + r * 8;
        int n  = n0 + tx;
        float w0 = W[(size_t)(2 * kp) * N + n];
        float w1 = W[(size_t)(2 * kp + 1) * N + n];
        u32 hi, lo; split2(w0, w1, hi, lo);
        th[ty + r * 8][tx] = hi;
        tl[ty + r * 8][tx] = lo;
    }
    __syncthreads();
#pragma unroll
    for (int r = 0; r < 4; r++) {
        int n  = n0 + ty + r * 8;
        int kp = kp0 + tx;
        oh[(size_t)n * K2 + kp] = th[tx][ty + r * 8];
        ol[(size_t)n * K2 + kp] = tl[tx][ty + r * 8];
    }
}

// ---------------- convert + transpose MoE weight (single fp16 pairs) ----------
__global__ __launch_bounds__(256)
void split_w_h_kernel(const float* __restrict__ W, u32* __restrict__ o,
                      int K, int N) {
    int K2 = K / 2;
    size_t eoffW = (size_t)blockIdx.z * K * N;
    size_t eoffO = (size_t)blockIdx.z * N * K2;
    __shared__ u32 th[32][33];
    int kp0 = blockIdx.x * 32, n0 = blockIdx.y * 32;
    int tx = threadIdx.x, ty = threadIdx.y;
#pragma unroll
    for (int r = 0; r < 4; r++) {
        int kp = kp0 + ty + r * 8;
        int n  = n0 + tx;
        float w0 = W[eoffW + (size_t)(2 * kp) * N + n];
        float w1 = W[eoffW + (size_t)(2 * kp + 1) * N + n];
        th[ty + r * 8][tx] = pack_h2(w0, w1);
    }
    __syncthreads();
#pragma unroll
    for (int r = 0; r < 4; r++) {
        int n  = n0 + ty + r * 8;
        int kp = kp0 + tx;
        o[eoffO + (size_t)n * K2 + kp] = th[tx][ty + r * 8];
    }
}

// ---------------- cp.async helpers ----------------
__device__ __forceinline__ void cp_async16z(void* dst, const void* src, int sz) {
    u32 d = (u32)__cvta_generic_to_shared(dst);
    asm volatile("cp.async.ca.shared.global [%0], [%1], 16, %2;\n"
                 :: "r"(d), "l"(src), "r"(sz) : "memory");
}
__device__ __forceinline__ void cp_commit() {
    asm volatile("cp.async.commit_group;\n" ::: "memory");
}
template<int N> __device__ __forceinline__ void cp_wait() {
    asm volatile("cp.async.wait_group %0;\n" :: "n"(N) : "memory");
}

// ---------------- mma ----------------
__device__ __forceinline__ void mma_bf16(float* d, const u32* a, const u32* b) {
    asm volatile(
        "mma.sync.aligned.m16n8k16.row.col.f32.bf16.bf16.f32 "
        "{%0,%1,%2,%3}, {%4,%5,%6,%7}, {%8,%9}, {%0,%1,%2,%3};\n"
        : "+f"(d[0]), "+f"(d[1]), "+f"(d[2]), "+f"(d[3])
        : "r"(a[0]), "r"(a[1]), "r"(a[2]), "r"(a[3]), "r"(b[0]), "r"(b[1]));
}
__device__ __forceinline__ void mma_f16(float* d, const u32* a, const u32* b) {
    asm volatile(
        "mma.sync.aligned.m16n8k16.row.col.f32.f16.f16.f32 "
        "{%0,%1,%2,%3}, {%4,%5,%6,%7}, {%8,%9}, {%0,%1,%2,%3};\n"
        : "+f"(d[0]), "+f"(d[1]), "+f"(d[2]), "+f"(d[3])
        : "r"(a[0]), "r"(a[1]), "r"(a[2]), "r"(a[3]), "r"(b[0]), "r"(b[1]));
}

#define BM 128
#define BN 128
#define KP 16            // k-pairs per tile (32 elements)
#define STR 20           // smem row stride in u32 (16 used + 4 pad)
#define ABUF (128*STR)   // 2560 u32 per array per buffer
#define GEMM_SMEM_BYTES  (8*ABUF*4 + BM*4)
#define GEMMH_SMEM_BYTES (6*ABUF*4 + BM*4)

// ---------------- bf16x2 3-pass GEMM (delta projection, MODE 0 only) ----------
__global__ __launch_bounds__(256, 1)
void gemm_bf(const u32* __restrict__ Ahi, const u32* __restrict__ Alo,
             const u32* __restrict__ Bhi, const u32* __restrict__ Blo,
             float* __restrict__ C1, const float* __restrict__ bias,
             int M, int Ncols, int K)
{
    extern __shared__ u32 sm[];

    int mblk = blockIdx.y;
    int nblk = blockIdx.x;
    int n0 = nblk * BN;
    int K2 = K / 2;
    int tid = threadIdx.x;

    int crow = tid >> 1;
    int cseg = (tid & 1) * 8;
    size_t abase = (size_t)(mblk * BM + crow) * K2 + cseg;
    size_t bbase = (size_t)(n0 + crow) * K2 + cseg;

    int wid = tid >> 5, lane = tid & 31;
    int g = lane >> 2, tig = lane & 3;
    int wm = wid >> 2, wn = wid & 3;

    float acc[4][4][4];
#pragma unroll
    for (int i = 0; i < 4; i++)
#pragma unroll
        for (int j = 0; j < 4; j++)
#pragma unroll
            for (int k = 0; k < 4; k++) acc[i][j][k] = 0.f;

    int KT = K2 / KP;
    int buf = 0;
    u32 sdst = crow * STR + cseg;

    {
        u32* s0 = sm;
        cp_async16z(s0 + 0*ABUF + sdst,     Ahi + abase,     16);
        cp_async16z(s0 + 0*ABUF + sdst + 4, Ahi + abase + 4, 16);
        cp_async16z(s0 + 1*ABUF + sdst,     Alo + abase,     16);
        cp_async16z(s0 + 1*ABUF + sdst + 4, Alo + abase + 4, 16);
        cp_async16z(s0 + 2*ABUF + sdst,     Bhi + bbase,     16);
        cp_async16z(s0 + 2*ABUF + sdst + 4, Bhi + bbase + 4, 16);
        cp_async16z(s0 + 3*ABUF + sdst,     Blo + bbase,     16);
        cp_async16z(s0 + 3*ABUF + sdst + 4, Blo + bbase + 4, 16);
        cp_commit();
    }

    for (int kt = 0; kt < KT; kt++) {
        if (kt + 1 < KT) {
            u32* s1 = sm + (buf ^ 1) * 4 * ABUF;
            size_t ao = abase + (size_t)(kt + 1) * KP;
            size_t bo = bbase + (size_t)(kt + 1) * KP;
            cp_async16z(s1 + 0*ABUF + sdst,     Ahi + ao,     16);
            cp_async16z(s1 + 0*ABUF + sdst + 4, Ahi + ao + 4, 16);
            cp_async16z(s1 + 1*ABUF + sdst,     Alo + ao,     16);
            cp_async16z(s1 + 1*ABUF + sdst + 4, Alo + ao + 4, 16);
            cp_async16z(s1 + 2*ABUF + sdst,     Bhi + bo,     16);
            cp_async16z(s1 + 2*ABUF + sdst + 4, Bhi + bo + 4, 16);
            cp_async16z(s1 + 3*ABUF + sdst,     Blo + bo,     16);
            cp_async16z(s1 + 3*ABUF + sdst + 4, Blo + bo + 4, 16);
            cp_commit();
            cp_wait<1>();
        } else {
            cp_wait<0>();
        }
        __syncthreads();

        const u32* sAh = sm + buf * 4 * ABUF;
        const u32* sAl = sAh + ABUF;
        const u32* sBh = sAh + 2 * ABUF;
        const u32* sBl = sAh + 3 * ABUF;

#pragma unroll
        for (int ks = 0; ks < 2; ks++) {
            int kb = ks * 8;
            u32 ah[4][4], al[4][4];
#pragma unroll
            for (int mt = 0; mt < 4; mt++) {
                int row = wm * 64 + mt * 16 + g;
                ah[mt][0] = sAh[row * STR + kb + tig];
                ah[mt][1] = sAh[(row + 8) * STR + kb + tig];
                ah[mt][2] = sAh[row * STR + kb + tig + 4];
                ah[mt][3] = sAh[(row + 8) * STR + kb + tig + 4];
                al[mt][0] = sAl[row * STR + kb + tig];
                al[mt][1] = sAl[(row + 8) * STR + kb + tig];
                al[mt][2] = sAl[row * STR + kb + tig + 4];
                al[mt][3] = sAl[(row + 8) * STR + kb + tig + 4];
            }
            u32 bh[4][2], bl[4][2];
#pragma unroll
            for (int nt = 0; nt < 4; nt++) {
                int col = wn * 32 + nt * 8 + g;
                bh[nt][0] = sBh[col * STR + kb + tig];
                bh[nt][1] = sBh[col * STR + kb + tig + 4];
                bl[nt][0] = sBl[col * STR + kb + tig];
                bl[nt][1] = sBl[col * STR + kb + tig + 4];
            }
#pragma unroll
            for (int mt = 0; mt < 4; mt++)
#pragma unroll
                for (int nt = 0; nt < 4; nt++) {
                    mma_bf16(acc[mt][nt], ah[mt], bh[nt]);
                    mma_bf16(acc[mt][nt], ah[mt], bl[nt]);
                    mma_bf16(acc[mt][nt], al[mt], bh[nt]);
                }
        }
        __syncthreads();
        buf ^= 1;
    }

#pragma unroll
    for (int mt = 0; mt < 4; mt++) {
#pragma unroll
        for (int half = 0; half < 2; half++) {
            int gr = mblk * BM + wm * 64 + mt * 16 + g + half * 8;
            float* orow = C1 + (size_t)gr * Ncols;
#pragma unroll
            for (int nt = 0; nt < 4; nt++) {
                int col = n0 + wn * 32 + nt * 8 + tig * 2;
                float v0 = softplusf(acc[mt][nt][half*2+0] + bias[col]);
                float v1 = softplusf(acc[mt][nt][half*2+1] + bias[col+1]);
                *(float2*)(orow + col) = make_float2(v0, v1);
            }
        }
    }
}

// ---------------- fp16 2-pass GEMM (MoE up/down) ----------
// MODE 1: A gathered via rowidx, dual B/C (nblk<16 -> B1/C1, else B2/C2)
// MODE 2: A compact rows; C1[rowidx[r],:] += acc (scatter)
template<int MODE>
__global__ __launch_bounds__(256, 1)
void gemm_hf(const u32* __restrict__ Ahi, const u32* __restrict__ Alo,
             const u32* __restrict__ B1, const u32* __restrict__ B2,
             float* __restrict__ C1, float* __restrict__ C2,
             int Ncols, int K,
             const int* __restrict__ rowidx, const int* __restrict__ cntp)
{
    extern __shared__ u32 sm[];
    int* sidx = (int*)(sm + 6 * ABUF);

    int M = *cntp;
    int mblk = blockIdx.y;
    if (mblk * BM >= M) return;
    int nblk = blockIdx.x;

    const u32* Bp = B1;
    float* Cout = C1;
    int nb = nblk;
    if (MODE == 1 && nblk >= 16) { Bp = B2; Cout = C2; nb = nblk - 16; }
    int n0 = nb * BN;
    int K2 = K / 2;
    int tid = threadIdx.x;

    for (int i = tid; i < BM; i += 256) {
        int gr = mblk * BM + i;
        sidx[i] = (gr < M) ? rowidx[gr] : -1;
    }
    __syncthreads();

    int crow = tid >> 1;
    int cseg = (tid & 1) * 8;
    int asz;
    size_t abase;
    if (MODE == 1) {
        int s = sidx[crow];
        asz = (s >= 0) ? 16 : 0;
        abase = (size_t)(s >= 0 ? s : 0) * K2 + cseg;
    } else {
        int gr = mblk * BM + crow;
        asz = (gr < M) ? 16 : 0;
        abase = (size_t)(gr < M ? gr : 0) * K2 + cseg;
    }
    size_t bbase = (size_t)(n0 + crow) * K2 + cseg;

    int wid = tid >> 5, lane = tid & 31;
    int g = lane >> 2, tig = lane & 3;
    int wm = wid >> 2, wn = wid & 3;

    float acc[4][4][4];
#pragma unroll
    for (int i = 0; i < 4; i++)
#pragma unroll
        for (int j = 0; j < 4; j++)
#pragma unroll
            for (int k = 0; k < 4; k++) acc[i][j][k] = 0.f;

    int KT = K2 / KP;
    int buf = 0;
    u32 sdst = crow * STR + cseg;

    {
        u32* s0 = sm;
        cp_async16z(s0 + 0*ABUF + sdst,     Ahi + abase,     asz);
        cp_async16z(s0 + 0*ABUF + sdst + 4, Ahi + abase + 4, asz);
        cp_async16z(s0 + 1*ABUF + sdst,     Alo + abase,     asz);
        cp_async16z(s0 + 1*ABUF + sdst + 4, Alo + abase + 4, asz);
        cp_async16z(s0 + 2*ABUF + sdst,     Bp + bbase,      16);
        cp_async16z(s0 + 2*ABUF + sdst + 4, Bp + bbase + 4,  16);
        cp_commit();
    }

    for (int kt = 0; kt < KT; kt++) {
        if (kt + 1 < KT) {
            u32* s1 = sm + (buf ^ 1) * 3 * ABUF;
            size_t ao = abase + (size_t)(kt + 1) * KP;
            size_t bo = bbase + (size_t)(kt + 1) * KP;
            cp_async16z(s1 + 0*ABUF + sdst,     Ahi + ao,     asz);
            cp_async16z(s1 + 0*ABUF + sdst + 4, Ahi + ao + 4, asz);
            cp_async16z(s1 + 1*ABUF + sdst,     Alo + ao,     asz);
            cp_async16z(s1 + 1*ABUF + sdst + 4, Alo + ao + 4, asz);
            cp_async16z(s1 + 2*ABUF + sdst,     Bp + bo,      16);
            cp_async16z(s1 + 2*ABUF + sdst + 4, Bp + bo + 4,  16);
            cp_commit();
            cp_wait<1>();
        } else {
            cp_wait<0>();
        }
        __syncthreads();

        const u32* sAh = sm + buf * 3 * ABUF;
        const u32* sAl = sAh + ABUF;
        const u32* sB  = sAh + 2 * ABUF;

#pragma unroll
        for (int ks = 0; ks < 2; ks++) {
            int kb = ks * 8;
            u32 ah[4][4], al[4][4];
#pragma unroll
            for (int mt = 0; mt < 4; mt++) {
                int row = wm * 64 + mt * 16 + g;
                ah[mt][0] = sAh[row * STR + kb + tig];
                ah[mt][1] = sAh[(row + 8) * STR + kb + tig];
                ah[mt][2] = sAh[row * STR + kb + tig + 4];
                ah[mt][3] = sAh[(row + 8) * STR + kb + tig + 4];
                al[mt][0] = sAl[row * STR + kb + tig];
                al[mt][1] = sAl[(row + 8) * STR + kb + tig];
                al[mt][2] = sAl[row * STR + kb + tig + 4];
                al[mt][3] = sAl[(row + 8) * STR + kb + tig + 4];
            }
            u32 bh[4][2];
#pragma unroll
            for (int nt = 0; nt < 4; nt++) {
                int col = wn * 32 + nt * 8 + g;
                bh[nt][0] = sB[col * STR + kb + tig];
                bh[nt][1] = sB[col * STR + kb + tig + 4];
            }
#pragma unroll
            for (int mt = 0; mt < 4; mt++)
#pragma unroll
                for (int nt = 0; nt < 4; nt++) {
                    mma_f16(acc[mt][nt], ah[mt], bh[nt]);
                    mma_f16(acc[mt][nt], al[mt], bh[nt]);
                }
        }
        __syncthreads();
        buf ^= 1;
    }

#pragma unroll
    for (int mt = 0; mt < 4; mt++) {
#pragma unroll
        for (int half = 0; half < 2; half++) {
            int lr = wm * 64 + mt * 16 + g + half * 8;
            int gr = mblk * BM + lr;
            if (gr >= M) continue;
            float* orow;
            if (MODE == 2) {
                int tok = sidx[lr];
                orow = C1 + (size_t)tok * Ncols;
            } else {
                orow = Cout + (size_t)gr * Ncols;
            }
#pragma unroll
            for (int nt = 0; nt < 4; nt++) {
                int col = n0 + wn * 32 + nt * 8 + tig * 2;
                float v0 = acc[mt][nt][half * 2 + 0];
                float v1 = acc[mt][nt][half * 2 + 1];
                if (MODE == 1) {
                    *(float2*)(orow + col) = make_float2(v0, v1);
                } else {
                    float2 old = *(float2*)(orow + col);
                    old.x += v0; old.y += v1;
                    *(float2*)(orow + col) = old;
                }
            }
        }
    }
}

// ---------------- small projections: Bm, Cm (from x) ----------------
__global__ __launch_bounds__(128)
void proj_small(const float* __restrict__ x, const float* __restrict__ WB,
                const float* __restrict__ WC)
{
    int n = blockIdx.x;
    __shared__ float xs[DD];
    const float* xr = x + (size_t)n * DD;
    for (int i = threadIdx.x; i < DD; i += 128) xs[i] = xr[i];
    __syncthreads();
    int warp = threadIdx.x >> 5, lane = threadIdx.x & 31;
    for (int c = warp; c < 32; c += 4) {
        const float* W; int col; float* out;
        if (c < 16) { W = WB; col = c;      out = g_Bm + (size_t)n * SS + col; }
        else        { W = WC; col = c - 16; out = g_Cm + (size_t)n * SS + col; }
        float s = 0.f;
        for (int k = lane; k < DD; k += 32)
            s = fmaf(xs[k], W[(size_t)k * SS + col], s);
        s += __shfl_xor_sync(~0u, s, 16);
        s += __shfl_xor_sync(~0u, s, 8);
        s += __shfl_xor_sync(~0u, s, 4);
        s += __shfl_xor_sync(~0u, s, 2);
        s += __shfl_xor_sync(~0u, s, 1);
        if (lane == 0) *out = s;
    }
}

// ---------------- selective scan (register partials + smem reduce) -------------
__global__ __launch_bounds__(256)
void scan_kernel(const float* __restrict__ x, const float* __restrict__ A_log,
                 const float* __restrict__ D_param)
{
    int b = blockIdx.x >> 6;
    int dchunk = blockIdx.x & 63;
    int dl = threadIdx.x >> 4;      // d-local 0..15
    int s  = threadIdx.x & 15;      // state index
    int d = dchunk * 16 + dl;

    float A_ds = -__expf(A_log[d * SS + s]);

    __shared__ float sx[16][16], sd[16][16];
    __shared__ float sB[16][17], sC[16][17];
    __shared__ float sp[16 * 272];  // [q][s*17 + dl]
    __shared__ float sDp[16];

    int tt = threadIdx.x >> 4;
    int cc = threadIdx.x & 15;
    const int base_bt = b * LL;

    if (threadIdx.x < 16) sDp[threadIdx.x] = D_param[dchunk * 16 + threadIdx.x];

    size_t xoff = ((size_t)(base_bt + tt)) * DD + dchunk * 16 + cc;
    float rx = x[xoff];
    float rd = g_delta[xoff];
    size_t boff = ((size_t)(base_bt + tt)) * SS + cc;
    float rB = g_Bm[boff];
    float rC = g_Cm[boff];

    float h = 0.f;
    for (int t0 = 0; t0 < LL; t0 += 16) {
        __syncthreads();
        sx[tt][cc] = rx; sd[tt][cc] = rd; sB[tt][cc] = rB; sC[tt][cc] = rC;
        __syncthreads();
        if (t0 + 16 < LL) {
            size_t xo = ((size_t)(base_bt + t0 + 16 + tt)) * DD + dchunk * 16 + cc;
            rx = x[xo]; rd = g_delta[xo];
            size_t bo = ((size_t)(base_bt + t0 + 16 + tt)) * SS + cc;
            rB = g_Bm[bo]; rC = g_Cm[bo];
        }
        float p[16];
#pragma unroll
        for (int q = 0; q < 16; q++) {
            float xv = sx[q][dl], dv = sd[q][dl];
            float Bv = sB[q][s],  Cv = sC[q][s];
            float a  = __expf(fminf(dv * A_ds, 10.f));
            float bBc = fminf(fmaxf(dv * Bv, -10.f), 10.f);
            h = fminf(fmaxf(a * h + bBc * xv, -10000.f), 10000.f);
            p[q] = h * Cv;
        }
#pragma unroll
        for (int q = 0; q < 16; q++)
            sp[q * 272 + s * 17 + dl] = p[q];
        __syncthreads();
        // reduction role: (q2 = tt, d2 = cc)
        float ysum = 0.f;
#pragma unroll
        for (int s2 = 0; s2 < 16; s2++)
            ysum += sp[tt * 272 + s2 * 17 + cc];
        float y = fmaf(sx[tt][cc], sDp[cc], ysum);
        size_t yo = ((size_t)(base_bt + t0 + tt)) * DD + dchunk * 16 + cc;
        g_ssm[yo] = y;
        g_acc[yo] = y;
        float yn = __shfl_down_sync(~0u, y, 1);
        if (!(cc & 1)) {
            float ya = fminf(fmaxf(y,  -60000.f), 60000.f);
            float yb = fminf(fmaxf(yn, -60000.f), 60000.f);
            u32 hi, lo; split2h(ya, yb, hi, lo);
            size_t po = ((size_t)(base_bt + t0 + tt)) * (DD/2) + dchunk * 8 + (cc >> 1);
            g_sHi[po] = hi;
            g_sLo[po] = lo;
        }
    }
}

// ---------------- router on SSM output: softmax, top-2, expert lists ----------
__global__ __launch_bounds__(128)
void router_kernel(const float* __restrict__ WR)
{
    int n = blockIdx.x;
    __shared__ float xs[DD];
    __shared__ float logits[EE];
    const float* xr = g_ssm + (size_t)n * DD;
    for (int i = threadIdx.x; i < DD; i += 128) xs[i] = xr[i];
    __syncthreads();
    int warp = threadIdx.x >> 5, lane = threadIdx.x & 31;
    {
        float s = 0.f;
        for (int k = lane; k < DD; k += 32)
            s = fmaf(xs[k], WR[(size_t)k * EE + warp], s);
        s += __shfl_xor_sync(~0u, s, 16);
        s += __shfl_xor_sync(~0u, s, 8);
        s += __shfl_xor_sync(~0u, s, 4);
        s += __shfl_xor_sync(~0u, s, 2);
        s += __shfl_xor_sync(~0u, s, 1);
        if (lane == 0) logits[warp] = s;
    }
    __syncthreads();
    if (threadIdx.x == 0) {
        float l[4] = {logits[0], logits[1], logits[2], logits[3]};
        float m = fmaxf(fmaxf(l[0], l[1]), fmaxf(l[2], l[3]));
        float e[4], sum = 0.f;
#pragma unroll
        for (int i = 0; i < 4; i++) { e[i] = __expf(l[i] - m); sum += e[i]; }
        float p[4];
#pragma unroll
        for (int i = 0; i < 4; i++) p[i] = e[i] / sum;
        int i0 = 0;
#pragma unroll
        for (int i = 1; i < 4; i++) if (p[i] > p[i0]) i0 = i;
        int i1 = -1;
#pragma unroll
        for (int i = 0; i < 4; i++) {
            if (i == i0) continue;
            if (i1 < 0 || p[i] > p[i1]) i1 = i;
        }
        float w0 = p[i0], w1 = p[i1];
        float sw = w0 + w1 + 1e-9f;
        w0 /= sw; w1 /= sw;
        int pos = atomicAdd(&g_cnt[i0], 1);
        g_list[i0*NN + pos] = n; g_cw[i0*NN + pos] = w0;
        pos = atomicAdd(&g_cnt[i1], 1);
        g_list[i1*NN + pos] = n; g_cw[i1*NN + pos] = w1;
    }
}

// ---------------- silu(G)*U -> rmsnorm(wn) -> * cw (fp16 split output) --------
__global__ __launch_bounds__(256)
void act_norm(const float* __restrict__ wn, const float* __restrict__ cw,
              const int* __restrict__ cntp)
{
    int i = blockIdx.x;
    if (i >= *cntp) return;
    __shared__ float buf[HH];
    __shared__ float red[8];
    float ss = 0.f;
    for (int j = threadIdx.x; j < HH; j += 256) {
        float g = g_G[(size_t)i * HH + j];
        float u = g_U[(size_t)i * HH + j];
        float v = (g / (1.f + __expf(-g))) * u;
        buf[j] = v;
        ss = fmaf(v, v, ss);
    }
    ss += __shfl_xor_sync(~0u, ss, 16);
    ss += __shfl_xor_sync(~0u, ss, 8);
    ss += __shfl_xor_sync(~0u, ss, 4);
    ss += __shfl_xor_sync(~0u, ss, 2);
    ss += __shfl_xor_sync(~0u, ss, 1);
    if ((threadIdx.x & 31) == 0) red[threadIdx.x >> 5] = ss;
    __syncthreads();
    if (threadIdx.x < 32) {
        float v = (threadIdx.x < 8) ? red[threadIdx.x] : 0.f;
        v += __shfl_xor_sync(~0u, v, 4);
        v += __shfl_xor_sync(~0u, v, 2);
        v += __shfl_xor_sync(~0u, v, 1);
        if (threadIdx.x == 0) red[0] = v;
    }
    __syncthreads();
    float scale = cw[i] * rsqrtf(red[0] / (float)HH + 1e-6f);
    for (int j2 = threadIdx.x; j2 < HH / 2; j2 += 256) {
        float v0 = wn[2 * j2]     * buf[2 * j2]     * scale;
        float v1 = wn[2 * j2 + 1] * buf[2 * j2 + 1] * scale;
        u32 hi, lo; split2h(v0, v1, hi, lo);
        g_aHi[(size_t)i * (HH/2) + j2] = hi;
        g_aLo[(size_t)i * (HH/2) + j2] = lo;
    }
}

// ---------------- final rmsnorm over (ssm + moe) ----------------
__global__ __launch_bounds__(256)
void final_norm(const float* __restrict__ norm_w, float* __restrict__ out)
{
    int n = blockIdx.x;
    __shared__ float red[8];
    float ss = 0.f;
    const float* row = g_acc + (size_t)n * DD;
    for (int j = threadIdx.x; j < DD; j += 256) {
        float v = row[j];
        ss = fmaf(v, v, ss);
    }
    ss += __shfl_xor_sync(~0u, ss, 16);
    ss += __shfl_xor_sync(~0u, ss, 8);
    ss += __shfl_xor_sync(~0u, ss, 4);
    ss += __shfl_xor_sync(~0u, ss, 2);
    ss += __shfl_xor_sync(~0u, ss, 1);
    if ((threadIdx.x & 31) == 0) red[threadIdx.x >> 5] = ss;
    __syncthreads();
    if (threadIdx.x < 32) {
        float v = (threadIdx.x < 8) ? red[threadIdx.x] : 0.f;
        v += __shfl_xor_sync(~0u, v, 4);
        v += __shfl_xor_sync(~0u, v, 2);
        v += __shfl_xor_sync(~0u, v, 1);
        if (threadIdx.x == 0) red[0] = v;
    }
    __syncthreads();
    float inv = rsqrtf(red[0] / (float)DD + 1e-6f);
    for (int j = threadIdx.x; j < DD; j += 256)
        out[(size_t)n * DD + j] = norm_w[j] * row[j] * inv;
}

// ---------------- launch ----------------
extern "C" void kernel_launch(void* const* d_in, const int* in_sizes, int n_in,
                              void* d_out, int out_size)
{
    const float* x        = (const float*)d_in[0];
    const float* A_log    = (const float*)d_in[1];
    const float* D_param  = (const float*)d_in[2];
    const float* W_delta  = (const float*)d_in[3];
    const float* b_delta  = (const float*)d_in[4];
    const float* W_B      = (const float*)d_in[5];
    const float* W_C      = (const float*)d_in[6];
    const float* W_router = (const float*)d_in[7];
    const float* Wg       = (const float*)d_in[8];
    const float* Wu       = (const float*)d_in[9];
    const float* Wd       = (const float*)d_in[10];
    const float* wn_exp   = (const float*)d_in[11];
    const float* norm_w   = (const float*)d_in[12];
    float* out = (float*)d_out;

    float *p_delta, *p_G, *p_U, *p_acc, *p_cw;
    int *p_cnt, *p_list;
    u32 *p_xHi, *p_xLo, *p_sHi, *p_sLo, *p_aHi, *p_aLo;
    u32 *p_WdHi, *p_WdLo, *p_WgF, *p_WuF, *p_WnF;
    cudaGetSymbolAddress((void**)&p_delta, g_delta);
    cudaGetSymbolAddress((void**)&p_G,     g_G);
    cudaGetSymbolAddress((void**)&p_U,     g_U);
    cudaGetSymbolAddress((void**)&p_acc,   g_acc);
    cudaGetSymbolAddress((void**)&p_cnt,   g_cnt);
    cudaGetSymbolAddress((void**)&p_list,  g_list);
    cudaGetSymbolAddress((void**)&p_cw,    g_cw);
    cudaGetSymbolAddress((void**)&p_xHi,   g_xHi);
    cudaGetSymbolAddress((void**)&p_xLo,   g_xLo);
    cudaGetSymbolAddress((void**)&p_sHi,   g_sHi);
    cudaGetSymbolAddress((void**)&p_sLo,   g_sLo);
    cudaGetSymbolAddress((void**)&p_aHi,   g_aHi);
    cudaGetSymbolAddress((void**)&p_aLo,   g_aLo);
    cudaGetSymbolAddress((void**)&p_WdHi,  g_WdHi);
    cudaGetSymbolAddress((void**)&p_WdLo,  g_WdLo);
    cudaGetSymbolAddress((void**)&p_WgF,   g_WgF);
    cudaGetSymbolAddress((void**)&p_WuF,   g_WuF);
    cudaGetSymbolAddress((void**)&p_WnF,   g_WnF);

    cudaFuncSetAttribute(gemm_bf,    cudaFuncAttributeMaxDynamicSharedMemorySize, GEMM_SMEM_BYTES);
    cudaFuncSetAttribute(gemm_hf<1>, cudaFuncAttributeMaxDynamicSharedMemorySize, GEMMH_SMEM_BYTES);
    cudaFuncSetAttribute(gemm_hf<2>, cudaFuncAttributeMaxDynamicSharedMemorySize, GEMMH_SMEM_BYTES);

    zero_counts<<<1, 32>>>();

    // operand pre-conversion
    {
        int n2 = NN * DD / 2;
        split_x_kernel<<<(n2 + 255) / 256, 256>>>(x, p_xHi, p_xLo, n2);
    }
    {
        dim3 blk(32, 8);
        dim3 gWdel(DD/2/32, DD/32, 1);
        split_w_kernel<<<gWdel, blk>>>(W_delta, p_WdHi, p_WdLo, DD, DD);
        dim3 gUp(DD/2/32, HH/32, EE);
        split_w_h_kernel<<<gUp, blk>>>(Wg, p_WgF, DD, HH);
        split_w_h_kernel<<<gUp, blk>>>(Wu, p_WuF, DD, HH);
        dim3 gDn(HH/2/32, DD/32, EE);
        split_w_h_kernel<<<gDn, blk>>>(Wd, p_WnF, HH, DD);
    }

    // delta = softplus(x @ W_delta + b)   [bf16x2 3-pass]
    {
        dim3 grid(DD / BN, NN / BM);
        gemm_bf<<<grid, 256, GEMM_SMEM_BYTES>>>(
            p_xHi, p_xLo, p_WdHi, p_WdLo, p_delta, b_delta, NN, DD, DD);
    }

    // Bm, Cm from x
    proj_small<<<NN, 128>>>(x, W_B, W_C);

    // selective scan -> g_ssm / g_acc / fp16-split ssm
    scan_kernel<<<BB * (DD / 16), 256>>>(x, A_log, D_param);

    // router on SSM output
    router_kernel<<<NN, 128>>>(W_router);

    // experts
    for (int e = 0; e < EE; e++) {
        const u32* WgF_e = p_WgF + (size_t)e * HH * (DD/2);
        const u32* WuF_e = p_WuF + (size_t)e * HH * (DD/2);
        const u32* WnF_e = p_WnF + (size_t)e * DD * (HH/2);
        const float* wn_e = wn_exp + (size_t)e * HH;
        const int* rowidx = p_list + (size_t)e * NN;
        const int* cntp   = p_cnt + e;
        const float* cwp  = p_cw + (size_t)e * NN;

        // G = gather(ssm) @ Wg_e ; U = gather(ssm) @ Wu_e  [fp16 2-pass]
        {
            dim3 grid(2 * HH / BN, NN / BM);   // nblk<16 -> G, else U
            gemm_hf<1><<<grid, 256, GEMMH_SMEM_BYTES>>>(
                p_sHi, p_sLo, WgF_e, WuF_e, p_G, p_U, HH, DD, rowidx, cntp);
        }
        // act = wn * rmsnorm(silu(G)*U) * cw  (fp16 split output)
        act_norm<<<NN, 256>>>(wn_e, cwp, cntp);
        // acc[token] += act @ Wd_e  [fp16 2-pass]
        {
            dim3 grid(DD / BN, NN / BM);
            gemm_hf<2><<<grid, 256, GEMMH_SMEM_BYTES>>>(
                p_aHi, p_aLo, WnF_e, nullptr, p_acc, nullptr, DD, HH, rowidx, cntp);
        }
    }

    // out = rmsnorm(ssm + moe, norm_w)
    final_norm<<<NN, 256>>>(norm_w, out);
}

// round 7
// speedup vs baseline: 2.8489x; 1.1277x over previous
#include <cuda_runtime.h>
#include <cuda_bf16.h>
#include <cuda_fp16.h>
#include <math.h>
#include <stdint.h>

// Problem dims (fixed)
#define BB 2
#define LL 2048
#define DD 1024
#define SS 16
#define EE 4
#define HH 2048
#define NN (BB*LL)   // 4096

typedef uint32_t u32;

// ---------------- scratch (device globals; no allocation allowed) ----------------
__device__ float g_delta[NN*DD];
__device__ float g_Bm[NN*SS];
__device__ float g_Cm[NN*SS];
__device__ float g_ssm[NN*DD];
__device__ float g_acc[NN*DD];
__device__ int   g_cnt[EE];
__device__ int   g_list[EE*NN];
__device__ float g_cw[EE*NN];
__device__ float g_G[NN*HH];
__device__ float g_U[NN*HH];

// bf16x2 split operands for delta GEMM (packed: low16 = even k, high16 = odd k)
__device__ u32 g_xHi[NN*DD/2],   g_xLo[NN*DD/2];      // x           [NN][512]
__device__ u32 g_WdHi[DD*DD/2],  g_WdLo[DD*DD/2];     // W_delta^T   [D][512]
// fp16x2 split A-operands for MoE GEMMs
__device__ u32 g_sHi[NN*DD/2],   g_sLo[NN*DD/2];      // ssm  (fp16 pairs)
__device__ u32 g_aHi[NN*HH/2],   g_aLo[NN*HH/2];      // act  (fp16 pairs)
// fp16 single-precision MoE weights (transposed, pair-packed)
__device__ u32 g_WgF[EE*HH*DD/2];                     // Wg^T  [e][H][512]
__device__ u32 g_WuF[EE*HH*DD/2];                     // Wu^T  [e][H][512]
__device__ u32 g_WnF[EE*DD*HH/2];                     // Wd^T  [e][D][1024]

__device__ __forceinline__ float softplusf(float z) {
    return (z > 20.f) ? z : log1pf(__expf(z));
}

__device__ __forceinline__ void split2(float a, float b, u32& hi, u32& lo) {
    __nv_bfloat16 ah = __float2bfloat16(a);
    __nv_bfloat16 bh = __float2bfloat16(b);
    float ra = a - __bfloat162float(ah);
    float rb = b - __bfloat162float(bh);
    __nv_bfloat16 al = __float2bfloat16(ra);
    __nv_bfloat16 bl = __float2bfloat16(rb);
    hi = ((u32)__bfloat16_as_ushort(bh) << 16) | __bfloat16_as_ushort(ah);
    lo = ((u32)__bfloat16_as_ushort(bl) << 16) | __bfloat16_as_ushort(al);
}

__device__ __forceinline__ u32 pack_h2(float a, float b) {
    __half2 h = __floats2half2_rn(a, b);
    return *reinterpret_cast<u32*>(&h);
}
__device__ __forceinline__ void split2h(float a, float b, u32& hi, u32& lo) {
    __half2 h = __floats2half2_rn(a, b);
    float2 hf = __half22float2(h);
    hi = *reinterpret_cast<u32*>(&h);
    __half2 l = __floats2half2_rn(a - hf.x, b - hf.y);
    lo = *reinterpret_cast<u32*>(&l);
}

// ---------------- zero counts ----------------
__global__ void zero_counts() {
    if (threadIdx.x < EE) g_cnt[threadIdx.x] = 0;
}

// ---------------- split x (bf16 pairs, row-major) ----------------
__global__ __launch_bounds__(256)
void split_x_kernel(const float* __restrict__ in, u32* __restrict__ oh,
                    u32* __restrict__ ol, int n2) {
    int i = blockIdx.x * blockDim.x + threadIdx.x;
    if (i < n2) {
        float2 v = ((const float2*)in)[i];
        u32 hi, lo; split2(v.x, v.y, hi, lo);
        oh[i] = hi; ol[i] = lo;
    }
}

// ---------------- split + transpose W_delta (bf16 pairs) ----------------
__global__ __launch_bounds__(256)
void split_w_kernel(const float* __restrict__ W, u32* __restrict__ oh,
                    u32* __restrict__ ol, int K, int N) {
    int K2 = K / 2;
    __shared__ u32 th[32][33], tl[32][33];
    int kp0 = blockIdx.x * 32, n0 = blockIdx.y * 32;
    int tx = threadIdx.x, ty = threadIdx.y;
#pragma unroll
    for (int r = 0; r < 4; r++) {
        int kp = kp0 + ty + r * 8;
        int n  = n0 + tx;
        float w0 = W[(size_t)(2 * kp) * N + n];
        float w1 = W[(size_t)(2 * kp + 1) * N + n];
        u32 hi, lo; split2(w0, w1, hi, lo);
        th[ty + r * 8][tx] = hi;
        tl[ty + r * 8][tx] = lo;
    }
    __syncthreads();
#pragma unroll
    for (int r = 0; r < 4; r++) {
        int n  = n0 + ty + r * 8;
        int kp = kp0 + tx;
        oh[(size_t)n * K2 + kp] = th[tx][ty + r * 8];
        ol[(size_t)n * K2 + kp] = tl[tx][ty + r * 8];
    }
}

// ---------------- convert + transpose MoE weight (single fp16 pairs) ----------
__global__ __launch_bounds__(256)
void split_w_h_kernel(const float* __restrict__ W, u32* __restrict__ o,
                      int K, int N) {
    int K2 = K / 2;
    size_t eoffW = (size_t)blockIdx.z * K * N;
    size_t eoffO = (size_t)blockIdx.z * N * K2;
    __shared__ u32 th[32][33];
    int kp0 = blockIdx.x * 32, n0 = blockIdx.y * 32;
    int tx = threadIdx.x, ty = threadIdx.y;
#pragma unroll
    for (int r = 0; r < 4; r++) {
        int kp = kp0 + ty + r * 8;
        int n  = n0 + tx;
        float w0 = W[eoffW + (size_t)(2 * kp) * N + n];
        float w1 = W[eoffW + (size_t)(2 * kp + 1) * N + n];
        th[ty + r * 8][tx] = pack_h2(w0, w1);
    }
    __syncthreads();
#pragma unroll
    for (int r = 0; r < 4; r++) {
        int n  = n0 + ty + r * 8;
        int kp = kp0 + tx;
        o[eoffO + (size_t)n * K2 + kp] = th[tx][ty + r * 8];
    }
}

// ---------------- cp.async helpers ----------------
__device__ __forceinline__ void cp_async16z(void* dst, const void* src, int sz) {
    u32 d = (u32)__cvta_generic_to_shared(dst);
    asm volatile("cp.async.ca.shared.global [%0], [%1], 16, %2;\n"
                 :: "r"(d), "l"(src), "r"(sz) : "memory");
}
__device__ __forceinline__ void cp_commit() {
    asm volatile("cp.async.commit_group;\n" ::: "memory");
}
template<int N> __device__ __forceinline__ void cp_wait() {
    asm volatile("cp.async.wait_group %0;\n" :: "n"(N) : "memory");
}

// ---------------- mma / ldmatrix ----------------
__device__ __forceinline__ void mma_bf16(float* d, const u32* a, const u32* b) {
    asm volatile(
        "mma.sync.aligned.m16n8k16.row.col.f32.bf16.bf16.f32 "
        "{%0,%1,%2,%3}, {%4,%5,%6,%7}, {%8,%9}, {%0,%1,%2,%3};\n"
        : "+f"(d[0]), "+f"(d[1]), "+f"(d[2]), "+f"(d[3])
        : "r"(a[0]), "r"(a[1]), "r"(a[2]), "r"(a[3]), "r"(b[0]), "r"(b[1]));
}
__device__ __forceinline__ void mma_f16(float* d, const u32* a, const u32* b) {
    asm volatile(
        "mma.sync.aligned.m16n8k16.row.col.f32.f16.f16.f32 "
        "{%0,%1,%2,%3}, {%4,%5,%6,%7}, {%8,%9}, {%0,%1,%2,%3};\n"
        : "+f"(d[0]), "+f"(d[1]), "+f"(d[2]), "+f"(d[3])
        : "r"(a[0]), "r"(a[1]), "r"(a[2]), "r"(a[3]), "r"(b[0]), "r"(b[1]));
}
__device__ __forceinline__ void ldsm_x4(u32& r0, u32& r1, u32& r2, u32& r3, u32 addr) {
    asm volatile("ldmatrix.sync.aligned.m8n8.x4.shared.b16 {%0,%1,%2,%3}, [%4];"
                 : "=r"(r0), "=r"(r1), "=r"(r2), "=r"(r3) : "r"(addr));
}

#define BM 128
#define BN 128
#define KP 16            // k-pairs per tile (32 elements)
#define STR 20           // smem row stride in u32 (16 used + 4 pad)
#define ABUF (128*STR)   // 2560 u32 per array per buffer
#define GEMM_SMEM_BYTES  (8*ABUF*4 + BM*4)
#define GEMMH_SMEM_BYTES (6*ABUF*4 + BM*4)

// ---------------- bf16x2 3-pass GEMM (delta projection) ----------
__global__ __launch_bounds__(256, 1)
void gemm_bf(const u32* __restrict__ Ahi, const u32* __restrict__ Alo,
             const u32* __restrict__ Bhi, const u32* __restrict__ Blo,
             float* __restrict__ C1, const float* __restrict__ bias,
             int M, int Ncols, int K)
{
    extern __shared__ u32 sm[];

    int mblk = blockIdx.y;
    int nblk = blockIdx.x;
    int n0 = nblk * BN;
    int K2 = K / 2;
    int tid = threadIdx.x;

    int crow = tid >> 1;
    int cseg = (tid & 1) * 8;
    size_t abase = (size_t)(mblk * BM + crow) * K2 + cseg;
    size_t bbase = (size_t)(n0 + crow) * K2 + cseg;

    int wid = tid >> 5, lane = tid & 31;
    int g = lane >> 2, tig = lane & 3;
    int wm = wid >> 2, wn = wid & 3;

    // ldmatrix lane address components (u32 units within an array)
    u32 aoffL = (u32)((wm * 64 + (lane & 15)) * STR + (lane >> 4) * 4);
    u32 boffL = (u32)((wn * 32 + ((lane >> 4) << 3) + (lane & 7)) * STR + ((lane >> 3) & 1) * 4);

    float acc[4][4][4];
#pragma unroll
    for (int i = 0; i < 4; i++)
#pragma unroll
        for (int j = 0; j < 4; j++)
#pragma unroll
            for (int k = 0; k < 4; k++) acc[i][j][k] = 0.f;

    int KT = K2 / KP;
    int buf = 0;
    u32 sdst = crow * STR + cseg;

    {
        u32* s0 = sm;
        cp_async16z(s0 + 0*ABUF + sdst,     Ahi + abase,     16);
        cp_async16z(s0 + 0*ABUF + sdst + 4, Ahi + abase + 4, 16);
        cp_async16z(s0 + 1*ABUF + sdst,     Alo + abase,     16);
        cp_async16z(s0 + 1*ABUF + sdst + 4, Alo + abase + 4, 16);
        cp_async16z(s0 + 2*ABUF + sdst,     Bhi + bbase,     16);
        cp_async16z(s0 + 2*ABUF + sdst + 4, Bhi + bbase + 4, 16);
        cp_async16z(s0 + 3*ABUF + sdst,     Blo + bbase,     16);
        cp_async16z(s0 + 3*ABUF + sdst + 4, Blo + bbase + 4, 16);
        cp_commit();
    }

    for (int kt = 0; kt < KT; kt++) {
        if (kt + 1 < KT) {
            u32* s1 = sm + (buf ^ 1) * 4 * ABUF;
            size_t ao = abase + (size_t)(kt + 1) * KP;
            size_t bo = bbase + (size_t)(kt + 1) * KP;
            cp_async16z(s1 + 0*ABUF + sdst,     Ahi + ao,     16);
            cp_async16z(s1 + 0*ABUF + sdst + 4, Ahi + ao + 4, 16);
            cp_async16z(s1 + 1*ABUF + sdst,     Alo + ao,     16);
            cp_async16z(s1 + 1*ABUF + sdst + 4, Alo + ao + 4, 16);
            cp_async16z(s1 + 2*ABUF + sdst,     Bhi + bo,     16);
            cp_async16z(s1 + 2*ABUF + sdst + 4, Bhi + bo + 4, 16);
            cp_async16z(s1 + 3*ABUF + sdst,     Blo + bo,     16);
            cp_async16z(s1 + 3*ABUF + sdst + 4, Blo + bo + 4, 16);
            cp_commit();
            cp_wait<1>();
        } else {
            cp_wait<0>();
        }
        __syncthreads();

        u32 aAh = (u32)__cvta_generic_to_shared(sm + buf * 4 * ABUF);
        u32 aAl = aAh + ABUF * 4;
        u32 aBh = aAh + 2 * ABUF * 4;
        u32 aBl = aAh + 3 * ABUF * 4;

#pragma unroll
        for (int ks = 0; ks < 2; ks++) {
            int kb = ks * 8;
            u32 ah[4][4], al[4][4];
#pragma unroll
            for (int mt = 0; mt < 4; mt++) {
                u32 off = (aoffL + mt * 16 * STR + kb) * 4;
                ldsm_x4(ah[mt][0], ah[mt][1], ah[mt][2], ah[mt][3], aAh + off);
                ldsm_x4(al[mt][0], al[mt][1], al[mt][2], al[mt][3], aAl + off);
            }
            u32 bh[4][2], bl[4][2];
#pragma unroll
            for (int np = 0; np < 2; np++) {
                u32 off = (boffL + np * 16 * STR + kb) * 4;
                ldsm_x4(bh[2*np][0], bh[2*np][1], bh[2*np+1][0], bh[2*np+1][1], aBh + off);
                ldsm_x4(bl[2*np][0], bl[2*np][1], bl[2*np+1][0], bl[2*np+1][1], aBl + off);
            }
#pragma unroll
            for (int mt = 0; mt < 4; mt++)
#pragma unroll
                for (int nt = 0; nt < 4; nt++) {
                    mma_bf16(acc[mt][nt], ah[mt], bh[nt]);
                    mma_bf16(acc[mt][nt], ah[mt], bl[nt]);
                    mma_bf16(acc[mt][nt], al[mt], bh[nt]);
                }
        }
        __syncthreads();
        buf ^= 1;
    }

#pragma unroll
    for (int mt = 0; mt < 4; mt++) {
#pragma unroll
        for (int half = 0; half < 2; half++) {
            int gr = mblk * BM + wm * 64 + mt * 16 + g + half * 8;
            float* orow = C1 + (size_t)gr * Ncols;
#pragma unroll
            for (int nt = 0; nt < 4; nt++) {
                int col = n0 + wn * 32 + nt * 8 + tig * 2;
                float v0 = softplusf(acc[mt][nt][half*2+0] + bias[col]);
                float v1 = softplusf(acc[mt][nt][half*2+1] + bias[col+1]);
                *(float2*)(orow + col) = make_float2(v0, v1);
            }
        }
    }
}

// ---------------- fp16 2-pass GEMM (MoE up/down) ----------
// MODE 1: A gathered via rowidx, dual B/C (nblk<16 -> B1/C1, else B2/C2)
// MODE 2: A compact rows; C1[rowidx[r],:] += acc (scatter)
template<int MODE>
__global__ __launch_bounds__(256, 1)
void gemm_hf(const u32* __restrict__ Ahi, const u32* __restrict__ Alo,
             const u32* __restrict__ B1, const u32* __restrict__ B2,
             float* __restrict__ C1, float* __restrict__ C2,
             int Ncols, int K,
             const int* __restrict__ rowidx, const int* __restrict__ cntp)
{
    extern __shared__ u32 sm[];
    int* sidx = (int*)(sm + 6 * ABUF);

    int M = *cntp;
    int mblk = blockIdx.y;
    if (mblk * BM >= M) return;
    int nblk = blockIdx.x;

    const u32* Bp = B1;
    float* Cout = C1;
    int nb = nblk;
    if (MODE == 1 && nblk >= 16) { Bp = B2; Cout = C2; nb = nblk - 16; }
    int n0 = nb * BN;
    int K2 = K / 2;
    int tid = threadIdx.x;

    for (int i = tid; i < BM; i += 256) {
        int gr = mblk * BM + i;
        sidx[i] = (gr < M) ? rowidx[gr] : -1;
    }
    __syncthreads();

    int crow = tid >> 1;
    int cseg = (tid & 1) * 8;
    int asz;
    size_t abase;
    if (MODE == 1) {
        int s = sidx[crow];
        asz = (s >= 0) ? 16 : 0;
        abase = (size_t)(s >= 0 ? s : 0) * K2 + cseg;
    } else {
        int gr = mblk * BM + crow;
        asz = (gr < M) ? 16 : 0;
        abase = (size_t)(gr < M ? gr : 0) * K2 + cseg;
    }
    size_t bbase = (size_t)(n0 + crow) * K2 + cseg;

    int wid = tid >> 5, lane = tid & 31;
    int g = lane >> 2, tig = lane & 3;
    int wm = wid >> 2, wn = wid & 3;

    u32 aoffL = (u32)((wm * 64 + (lane & 15)) * STR + (lane >> 4) * 4);
    u32 boffL = (u32)((wn * 32 + ((lane >> 4) << 3) + (lane & 7)) * STR + ((lane >> 3) & 1) * 4);

    float acc[4][4][4];
#pragma unroll
    for (int i = 0; i < 4; i++)
#pragma unroll
        for (int j = 0; j < 4; j++)
#pragma unroll
            for (int k = 0; k < 4; k++) acc[i][j][k] = 0.f;

    int KT = K2 / KP;
    int buf = 0;
    u32 sdst = crow * STR + cseg;

    {
        u32* s0 = sm;
        cp_async16z(s0 + 0*ABUF + sdst,     Ahi + abase,     asz);
        cp_async16z(s0 + 0*ABUF + sdst + 4, Ahi + abase + 4, asz);
        cp_async16z(s0 + 1*ABUF + sdst,     Alo + abase,     asz);
        cp_async16z(s0 + 1*ABUF + sdst + 4, Alo + abase + 4, asz);
        cp_async16z(s0 + 2*ABUF + sdst,     Bp + bbase,      16);
        cp_async16z(s0 + 2*ABUF + sdst + 4, Bp + bbase + 4,  16);
        cp_commit();
    }

    for (int kt = 0; kt < KT; kt++) {
        if (kt + 1 < KT) {
            u32* s1 = sm + (buf ^ 1) * 3 * ABUF;
            size_t ao = abase + (size_t)(kt + 1) * KP;
            size_t bo = bbase + (size_t)(kt + 1) * KP;
            cp_async16z(s1 + 0*ABUF + sdst,     Ahi + ao,     asz);
            cp_async16z(s1 + 0*ABUF + sdst + 4, Ahi + ao + 4, asz);
            cp_async16z(s1 + 1*ABUF + sdst,     Alo + ao,     asz);
            cp_async16z(s1 + 1*ABUF + sdst + 4, Alo + ao + 4, asz);
            cp_async16z(s1 + 2*ABUF + sdst,     Bp + bo,      16);
            cp_async16z(s1 + 2*ABUF + sdst + 4, Bp + bo + 4,  16);
            cp_commit();
            cp_wait<1>();
        } else {
            cp_wait<0>();
        }
        __syncthreads();

        u32 aAh = (u32)__cvta_generic_to_shared(sm + buf * 3 * ABUF);
        u32 aAl = aAh + ABUF * 4;
        u32 aB  = aAh + 2 * ABUF * 4;

#pragma unroll
        for (int ks = 0; ks < 2; ks++) {
            int kb = ks * 8;
            u32 ah[4][4], al[4][4];
#pragma unroll
            for (int mt = 0; mt < 4; mt++) {
                u32 off = (aoffL + mt * 16 * STR + kb) * 4;
                ldsm_x4(ah[mt][0], ah[mt][1], ah[mt][2], ah[mt][3], aAh + off);
                ldsm_x4(al[mt][0], al[mt][1], al[mt][2], al[mt][3], aAl + off);
            }
            u32 bh[4][2];
#pragma unroll
            for (int np = 0; np < 2; np++) {
                u32 off = (boffL + np * 16 * STR + kb) * 4;
                ldsm_x4(bh[2*np][0], bh[2*np][1], bh[2*np+1][0], bh[2*np+1][1], aB + off);
            }
#pragma unroll
            for (int mt = 0; mt < 4; mt++)
#pragma unroll
                for (int nt = 0; nt < 4; nt++) {
                    mma_f16(acc[mt][nt], ah[mt], bh[nt]);
                    mma_f16(acc[mt][nt], al[mt], bh[nt]);
                }
        }
        __syncthreads();
        buf ^= 1;
    }

#pragma unroll
    for (int mt = 0; mt < 4; mt++) {
#pragma unroll
        for (int half = 0; half < 2; half++) {
            int lr = wm * 64 + mt * 16 + g + half * 8;
            int gr = mblk * BM + lr;
            if (gr >= M) continue;
            float* orow;
            if (MODE == 2) {
                int tok = sidx[lr];
                orow = C1 + (size_t)tok * Ncols;
            } else {
                orow = Cout + (size_t)gr * Ncols;
            }
#pragma unroll
            for (int nt = 0; nt < 4; nt++) {
                int col = n0 + wn * 32 + nt * 8 + tig * 2;
                float v0 = acc[mt][nt][half * 2 + 0];
                float v1 = acc[mt][nt][half * 2 + 1];
                if (MODE == 1) {
                    *(float2*)(orow + col) = make_float2(v0, v1);
                } else {
                    float2 old = *(float2*)(orow + col);
                    old.x += v0; old.y += v1;
                    *(float2*)(orow + col) = old;
                }
            }
        }
    }
}

// ---------------- small projections: Bm, Cm (from x) ----------------
__global__ __launch_bounds__(128)
void proj_small(const float* __restrict__ x, const float* __restrict__ WB,
                const float* __restrict__ WC)
{
    int n = blockIdx.x;
    __shared__ float xs[DD];
    const float* xr = x + (size_t)n * DD;
    for (int i = threadIdx.x; i < DD; i += 128) xs[i] = xr[i];
    __syncthreads();
    int warp = threadIdx.x >> 5, lane = threadIdx.x & 31;
    for (int c = warp; c < 32; c += 4) {
        const float* W; int col; float* out;
        if (c < 16) { W = WB; col = c;      out = g_Bm + (size_t)n * SS + col; }
        else        { W = WC; col = c - 16; out = g_Cm + (size_t)n * SS + col; }
        float s = 0.f;
        for (int k = lane; k < DD; k += 32)
            s = fmaf(xs[k], W[(size_t)k * SS + col], s);
        s += __shfl_xor_sync(~0u, s, 16);
        s += __shfl_xor_sync(~0u, s, 8);
        s += __shfl_xor_sync(~0u, s, 4);
        s += __shfl_xor_sync(~0u, s, 2);
        s += __shfl_xor_sync(~0u, s, 1);
        if (lane == 0) *out = s;
    }
}

// ---------------- selective scan (register partials + smem reduce) -------------
__global__ __launch_bounds__(256)
void scan_kernel(const float* __restrict__ x, const float* __restrict__ A_log,
                 const float* __restrict__ D_param)
{
    int b = blockIdx.x >> 6;
    int dchunk = blockIdx.x & 63;
    int dl = threadIdx.x >> 4;      // d-local 0..15
    int s  = threadIdx.x & 15;      // state index
    int d = dchunk * 16 + dl;

    float A_ds = -__expf(A_log[d * SS + s]);

    __shared__ float sx[16][16], sd[16][16];
    __shared__ float sB[16][17], sC[16][17];
    __shared__ float sp[16 * 272];  // [q][s*17 + dl]
    __shared__ float sDp[16];

    int tt = threadIdx.x >> 4;
    int cc = threadIdx.x & 15;
    const int base_bt = b * LL;

    if (threadIdx.x < 16) sDp[threadIdx.x] = D_param[dchunk * 16 + threadIdx.x];

    size_t xoff = ((size_t)(base_bt + tt)) * DD + dchunk * 16 + cc;
    float rx = x[xoff];
    float rd = g_delta[xoff];
    size_t boff = ((size_t)(base_bt + tt)) * SS + cc;
    float rB = g_Bm[boff];
    float rC = g_Cm[boff];

    float h = 0.f;
    for (int t0 = 0; t0 < LL; t0 += 16) {
        __syncthreads();
        sx[tt][cc] = rx; sd[tt][cc] = rd; sB[tt][cc] = rB; sC[tt][cc] = rC;
        __syncthreads();
        if (t0 + 16 < LL) {
            size_t xo = ((size_t)(base_bt + t0 + 16 + tt)) * DD + dchunk * 16 + cc;
            rx = x[xo]; rd = g_delta[xo];
            size_t bo = ((size_t)(base_bt + t0 + 16 + tt)) * SS + cc;
            rB = g_Bm[bo]; rC = g_Cm[bo];
        }
        float p[16];
#pragma unroll
        for (int q = 0; q < 16; q++) {
            float xv = sx[q][dl], dv = sd[q][dl];
            float Bv = sB[q][s],  Cv = sC[q][s];
            float a  = __expf(fminf(dv * A_ds, 10.f));
            float bBc = fminf(fmaxf(dv * Bv, -10.f), 10.f);
            h = fminf(fmaxf(a * h + bBc * xv, -10000.f), 10000.f);
            p[q] = h * Cv;
        }
#pragma unroll
        for (int q = 0; q < 16; q++)
            sp[q * 272 + s * 17 + dl] = p[q];
        __syncthreads();
        // reduction role: (q2 = tt, d2 = cc)
        float ysum = 0.f;
#pragma unroll
        for (int s2 = 0; s2 < 16; s2++)
            ysum += sp[tt * 272 + s2 * 17 + cc];
        float y = fmaf(sx[tt][cc], sDp[cc], ysum);
        size_t yo = ((size_t)(base_bt + t0 + tt)) * DD + dchunk * 16 + cc;
        g_ssm[yo] = y;
        g_acc[yo] = y;
        float yn = __shfl_down_sync(~0u, y, 1);
        if (!(cc & 1)) {
            float ya = fminf(fmaxf(y,  -60000.f), 60000.f);
            float yb = fminf(fmaxf(yn, -60000.f), 60000.f);
            u32 hi, lo; split2h(ya, yb, hi, lo);
            size_t po = ((size_t)(base_bt + t0 + tt)) * (DD/2) + dchunk * 8 + (cc >> 1);
            g_sHi[po] = hi;
            g_sLo[po] = lo;
        }
    }
}

// ---------------- router on SSM output: softmax, top-2, expert lists ----------
__global__ __launch_bounds__(128)
void router_kernel(const float* __restrict__ WR)
{
    int n = blockIdx.x;
    __shared__ float xs[DD];
    __shared__ float logits[EE];
    const float* xr = g_ssm + (size_t)n * DD;
    for (int i = threadIdx.x; i < DD; i += 128) xs[i] = xr[i];
    __syncthreads();
    int warp = threadIdx.x >> 5, lane = threadIdx.x & 31;
    {
        float s = 0.f;
        for (int k = lane; k < DD; k += 32)
            s = fmaf(xs[k], WR[(size_t)k * EE + warp], s);
        s += __shfl_xor_sync(~0u, s, 16);
        s += __shfl_xor_sync(~0u, s, 8);
        s += __shfl_xor_sync(~0u, s, 4);
        s += __shfl_xor_sync(~0u, s, 2);
        s += __shfl_xor_sync(~0u, s, 1);
        if (lane == 0) logits[warp] = s;
    }
    __syncthreads();
    if (threadIdx.x == 0) {
        float l[4] = {logits[0], logits[1], logits[2], logits[3]};
        float m = fmaxf(fmaxf(l[0], l[1]), fmaxf(l[2], l[3]));
        float e[4], sum = 0.f;
#pragma unroll
        for (int i = 0; i < 4; i++) { e[i] = __expf(l[i] - m); sum += e[i]; }
        float p[4];
#pragma unroll
        for (int i = 0; i < 4; i++) p[i] = e[i] / sum;
        int i0 = 0;
#pragma unroll
        for (int i = 1; i < 4; i++) if (p[i] > p[i0]) i0 = i;
        int i1 = -1;
#pragma unroll
        for (int i = 0; i < 4; i++) {
            if (i == i0) continue;
            if (i1 < 0 || p[i] > p[i1]) i1 = i;
        }
        float w0 = p[i0], w1 = p[i1];
        float sw = w0 + w1 + 1e-9f;
        w0 /= sw; w1 /= sw;
        int pos = atomicAdd(&g_cnt[i0], 1);
        g_list[i0*NN + pos] = n; g_cw[i0*NN + pos] = w0;
        pos = atomicAdd(&g_cnt[i1], 1);
        g_list[i1*NN + pos] = n; g_cw[i1*NN + pos] = w1;
    }
}

// ---------------- silu(G)*U -> rmsnorm(wn) -> * cw (fp16 split output) --------
__global__ __launch_bounds__(256)
void act_norm(const float* __restrict__ wn, const float* __restrict__ cw,
              const int* __restrict__ cntp)
{
    int i = blockIdx.x;
    if (i >= *cntp) return;
    __shared__ float buf[HH];
    __shared__ float red[8];
    float ss = 0.f;
    for (int j = threadIdx.x; j < HH; j += 256) {
        float g = g_G[(size_t)i * HH + j];
        float u = g_U[(size_t)i * HH + j];
        float v = (g / (1.f + __expf(-g))) * u;
        buf[j] = v;
        ss = fmaf(v, v, ss);
    }
    ss += __shfl_xor_sync(~0u, ss, 16);
    ss += __shfl_xor_sync(~0u, ss, 8);
    ss += __shfl_xor_sync(~0u, ss, 4);
    ss += __shfl_xor_sync(~0u, ss, 2);
    ss += __shfl_xor_sync(~0u, ss, 1);
    if ((threadIdx.x & 31) == 0) red[threadIdx.x >> 5] = ss;
    __syncthreads();
    if (threadIdx.x < 32) {
        float v = (threadIdx.x < 8) ? red[threadIdx.x] : 0.f;
        v += __shfl_xor_sync(~0u, v, 4);
        v += __shfl_xor_sync(~0u, v, 2);
        v += __shfl_xor_sync(~0u, v, 1);
        if (threadIdx.x == 0) red[0] = v;
    }
    __syncthreads();
    float scale = cw[i] * rsqrtf(red[0] / (float)HH + 1e-6f);
    for (int j2 = threadIdx.x; j2 < HH / 2; j2 += 256) {
        float v0 = wn[2 * j2]     * buf[2 * j2]     * scale;
        float v1 = wn[2 * j2 + 1] * buf[2 * j2 + 1] * scale;
        u32 hi, lo; split2h(v0, v1, hi, lo);
        g_aHi[(size_t)i * (HH/2) + j2] = hi;
        g_aLo[(size_t)i * (HH/2) + j2] = lo;
    }
}

// ---------------- final rmsnorm over (ssm + moe) ----------------
__global__ __launch_bounds__(256)
void final_norm(const float* __restrict__ norm_w, float* __restrict__ out)
{
    int n = blockIdx.x;
    __shared__ float red[8];
    float ss = 0.f;
    const float* row = g_acc + (size_t)n * DD;
    for (int j = threadIdx.x; j < DD; j += 256) {
        float v = row[j];
        ss = fmaf(v, v, ss);
    }
    ss += __shfl_xor_sync(~0u, ss, 16);
    ss += __shfl_xor_sync(~0u, ss, 8);
    ss += __shfl_xor_sync(~0u, ss, 4);
    ss += __shfl_xor_sync(~0u, ss, 2);
    ss += __shfl_xor_sync(~0u, ss, 1);
    if ((threadIdx.x & 31) == 0) red[threadIdx.x >> 5] = ss;
    __syncthreads();
    if (threadIdx.x < 32) {
        float v = (threadIdx.x < 8) ? red[threadIdx.x] : 0.f;
        v += __shfl_xor_sync(~0u, v, 4);
        v += __shfl_xor_sync(~0u, v, 2);
        v += __shfl_xor_sync(~0u, v, 1);
        if (threadIdx.x == 0) red[0] = v;
    }
    __syncthreads();
    float inv = rsqrtf(red[0] / (float)DD + 1e-6f);
    for (int j = threadIdx.x; j < DD; j += 256)
        out[(size_t)n * DD + j] = norm_w[j] * row[j] * inv;
}

// ---------------- launch ----------------
extern "C" void kernel_launch(void* const* d_in, const int* in_sizes, int n_in,
                              void* d_out, int out_size)
{
    const float* x        = (const float*)d_in[0];
    const float* A_log    = (const float*)d_in[1];
    const float* D_param  = (const float*)d_in[2];
    const float* W_delta  = (const float*)d_in[3];
    const float* b_delta  = (const float*)d_in[4];
    const float* W_B      = (const float*)d_in[5];
    const float* W_C      = (const float*)d_in[6];
    const float* W_router = (const float*)d_in[7];
    const float* Wg       = (const float*)d_in[8];
    const float* Wu       = (const float*)d_in[9];
    const float* Wd       = (const float*)d_in[10];
    const float* wn_exp   = (const float*)d_in[11];
    const float* norm_w   = (const float*)d_in[12];
    float* out = (float*)d_out;

    float *p_delta, *p_G, *p_U, *p_acc, *p_cw;
    int *p_cnt, *p_list;
    u32 *p_xHi, *p_xLo, *p_sHi, *p_sLo, *p_aHi, *p_aLo;
    u32 *p_WdHi, *p_WdLo, *p_WgF, *p_WuF, *p_WnF;
    cudaGetSymbolAddress((void**)&p_delta, g_delta);
    cudaGetSymbolAddress((void**)&p_G,     g_G);
    cudaGetSymbolAddress((void**)&p_U,     g_U);
    cudaGetSymbolAddress((void**)&p_acc,   g_acc);
    cudaGetSymbolAddress((void**)&p_cnt,   g_cnt);
    cudaGetSymbolAddress((void**)&p_list,  g_list);
    cudaGetSymbolAddress((void**)&p_cw,    g_cw);
    cudaGetSymbolAddress((void**)&p_xHi,   g_xHi);
    cudaGetSymbolAddress((void**)&p_xLo,   g_xLo);
    cudaGetSymbolAddress((void**)&p_sHi,   g_sHi);
    cudaGetSymbolAddress((void**)&p_sLo,   g_sLo);
    cudaGetSymbolAddress((void**)&p_aHi,   g_aHi);
    cudaGetSymbolAddress((void**)&p_aLo,   g_aLo);
    cudaGetSymbolAddress((void**)&p_WdHi,  g_WdHi);
    cudaGetSymbolAddress((void**)&p_WdLo,  g_WdLo);
    cudaGetSymbolAddress((void**)&p_WgF,   g_WgF);
    cudaGetSymbolAddress((void**)&p_WuF,   g_WuF);
    cudaGetSymbolAddress((void**)&p_WnF,   g_WnF);

    cudaFuncSetAttribute(gemm_bf,    cudaFuncAttributeMaxDynamicSharedMemorySize, GEMM_SMEM_BYTES);
    cudaFuncSetAttribute(gemm_hf<1>, cudaFuncAttributeMaxDynamicSharedMemorySize, GEMMH_SMEM_BYTES);
    cudaFuncSetAttribute(gemm_hf<2>, cudaFuncAttributeMaxDynamicSharedMemorySize, GEMMH_SMEM_BYTES);

    zero_counts<<<1, 32>>>();

    // operand pre-conversion
    {
        int n2 = NN * DD / 2;
        split_x_kernel<<<(n2 + 255) / 256, 256>>>(x, p_xHi, p_xLo, n2);
    }
    {
        dim3 blk(32, 8);
        dim3 gWdel(DD/2/32, DD/32, 1);
        split_w_kernel<<<gWdel, blk>>>(W_delta, p_WdHi, p_WdLo, DD, DD);
        dim3 gUp(DD/2/32, HH/32, EE);
        split_w_h_kernel<<<gUp, blk>>>(Wg, p_WgF, DD, HH);
        split_w_h_kernel<<<gUp, blk>>>(Wu, p_WuF, DD, HH);
        dim3 gDn(HH/2/32, DD/32, EE);
        split_w_h_kernel<<<gDn, blk>>>(Wd, p_WnF, HH, DD);
    }

    // delta = softplus(x @ W_delta + b)   [bf16x2 3-pass]
    {
        dim3 grid(DD / BN, NN / BM);
        gemm_bf<<<grid, 256, GEMM_SMEM_BYTES>>>(
            p_xHi, p_xLo, p_WdHi, p_WdLo, p_delta, b_delta, NN, DD, DD);
    }

    // Bm, Cm from x
    proj_small<<<NN, 128>>>(x, W_B, W_C);

    // selective scan -> g_ssm / g_acc / fp16-split ssm
    scan_kernel<<<BB * (DD / 16), 256>>>(x, A_log, D_param);

    // router on SSM output
    router_kernel<<<NN, 128>>>(W_router);

    // experts
    for (int e = 0; e < EE; e++) {
        const u32* WgF_e = p_WgF + (size_t)e * HH * (DD/2);
        const u32* WuF_e = p_WuF + (size_t)e * HH * (DD/2);
        const u32* WnF_e = p_WnF + (size_t)e * DD * (HH/2);
        const float* wn_e = wn_exp + (size_t)e * HH;
        const int* rowidx = p_list + (size_t)e * NN;
        const int* cntp   = p_cnt + e;
        const float* cwp  = p_cw + (size_t)e * NN;

        // G = gather(ssm) @ Wg_e ; U = gather(ssm) @ Wu_e  [fp16 2-pass]
        {
            dim3 grid(2 * HH / BN, NN / BM);   // nblk<16 -> G, else U
            gemm_hf<1><<<grid, 256, GEMMH_SMEM_BYTES>>>(
                p_sHi, p_sLo, WgF_e, WuF_e, p_G, p_U, HH, DD, rowidx, cntp);
        }
        // act = wn * rmsnorm(silu(G)*U) * cw  (fp16 split output)
        act_norm<<<NN, 256>>>(wn_e, cwp, cntp);
        // acc[token] += act @ Wd_e  [fp16 2-pass]
        {
            dim3 grid(DD / BN, NN / BM);
            gemm_hf<2><<<grid, 256, GEMMH_SMEM_BYTES>>>(
                p_aHi, p_aLo, WnF_e, nullptr, p_acc, nullptr, DD, HH, rowidx, cntp);
        }
    }

    // out = rmsnorm(ssm + moe, norm_w)
    final_norm<<<NN, 256>>>(norm_w, out);
}

// round 9
// speedup vs baseline: 3.3996x; 1.1933x over previous
#include <cuda_runtime.h>
#include <cuda_bf16.h>
#include <cuda_fp16.h>
#include <math.h>
#include <stdint.h>

// Problem dims (fixed)
#define BB 2
#define LL 2048
#define DD 1024
#define SS 16
#define EE 4
#define HH 2048
#define NN (BB*LL)   // 4096

typedef uint32_t u32;

// ---------------- scratch (device globals; no allocation allowed) ----------------
__device__ float g_delta[NN*DD];
__device__ float g_Bm[NN*SS];
__device__ float g_Cm[NN*SS];
__device__ float g_ssm[NN*DD];
__device__ float g_acc[NN*DD];
__device__ int   g_cnt[EE];
__device__ int   g_list[EE*NN];
__device__ float g_cw[EE*NN];
__device__ float g_G[NN*HH];
__device__ float g_U[NN*HH];

// bf16x2 split operands for delta GEMM (packed: low16 = even k, high16 = odd k)
__device__ u32 g_xHi[NN*DD/2],   g_xLo[NN*DD/2];      // x           [NN][512]
__device__ u32 g_WdHi[DD*DD/2],  g_WdLo[DD*DD/2];     // W_delta^T   [D][512]
// fp16 single-precision MoE operands (pair-packed)
__device__ u32 g_sF[NN*DD/2];                         // ssm  (fp16 pairs)
__device__ u32 g_aF[NN*HH/2];                         // act  (fp16 pairs)
__device__ u32 g_WgF[EE*HH*DD/2];                     // Wg^T  [e][H][512]
__device__ u32 g_WuF[EE*HH*DD/2];                     // Wu^T  [e][H][512]
__device__ u32 g_WnF[EE*DD*HH/2];                     // Wd^T  [e][D][1024]

__device__ __forceinline__ float softplusf(float z) {
    return (z > 20.f) ? z : log1pf(__expf(z));
}

__device__ __forceinline__ void split2(float a, float b, u32& hi, u32& lo) {
    __nv_bfloat16 ah = __float2bfloat16(a);
    __nv_bfloat16 bh = __float2bfloat16(b);
    float ra = a - __bfloat162float(ah);
    float rb = b - __bfloat162float(bh);
    __nv_bfloat16 al = __float2bfloat16(ra);
    __nv_bfloat16 bl = __float2bfloat16(rb);
    hi = ((u32)__bfloat16_as_ushort(bh) << 16) | __bfloat16_as_ushort(ah);
    lo = ((u32)__bfloat16_as_ushort(bl) << 16) | __bfloat16_as_ushort(al);
}

__device__ __forceinline__ u32 pack_h2(float a, float b) {
    __half2 h = __floats2half2_rn(a, b);
    return *reinterpret_cast<u32*>(&h);
}

// ---------------- zero counts ----------------
__global__ void zero_counts() {
    if (threadIdx.x < EE) g_cnt[threadIdx.x] = 0;
}

// ---------------- split x (bf16 pairs, row-major) ----------------
__global__ __launch_bounds__(256)
void split_x_kernel(const float* __restrict__ in, u32* __restrict__ oh,
                    u32* __restrict__ ol, int n2) {
    int i = blockIdx.x * blockDim.x + threadIdx.x;
    if (i < n2) {
        float2 v = ((const float2*)in)[i];
        u32 hi, lo; split2(v.x, v.y, hi, lo);
        oh[i] = hi; ol[i] = lo;
    }
}

// ---------------- split + transpose W_delta (bf16 pairs) ----------------
__global__ __launch_bounds__(256)
void split_w_kernel(const float* __restrict__ W, u32* __restrict__ oh,
                    u32* __restrict__ ol, int K, int N) {
    int K2 = K / 2;
    __shared__ u32 th[32][33], tl[32][33];
    int kp0 = blockIdx.x * 32, n0 = blockIdx.y * 32;
    int tx = threadIdx.x, ty = threadIdx.y;
#pragma unroll
    for (int r = 0; r < 4; r++) {
        int kp = kp0 + ty + r * 8;
        int n  = n0 + tx;
        float w0 = W[(size_t)(2 * kp) * N + n];
        float w1 = W[(size_t)(2 * kp + 1) * N + n];
        u32 hi, lo; split2(w0, w1, hi, lo);
        th[ty + r * 8][tx] = hi;
        tl[ty + r * 8][tx] = lo;
    }
    __syncthreads();
#pragma unroll
    for (int r = 0; r < 4; r++) {
        int n  = n0 + ty + r * 8;
        int kp = kp0 + tx;
        oh[(size_t)n * K2 + kp] = th[tx][ty + r * 8];
        ol[(size_t)n * K2 + kp] = tl[tx][ty + r * 8];
    }
}

// ---------------- convert + transpose MoE weight (single fp16 pairs) ----------
__global__ __launch_bounds__(256)
void split_w_h_kernel(const float* __restrict__ W, u32* __restrict__ o,
                      int K, int N) {
    int K2 = K / 2;
    size_t eoffW = (size_t)blockIdx.z * K * N;
    size_t eoffO = (size_t)blockIdx.z * N * K2;
    __shared__ u32 th[32][33];
    int kp0 = blockIdx.x * 32, n0 = blockIdx.y * 32;
    int tx = threadIdx.x, ty = threadIdx.y;
#pragma unroll
    for (int r = 0; r < 4; r++) {
        int kp = kp0 + ty + r * 8;
        int n  = n0 + tx;
        float w0 = W[eoffW + (size_t)(2 * kp) * N + n];
        float w1 = W[eoffW + (size_t)(2 * kp + 1) * N + n];
        th[ty + r * 8][tx] = pack_h2(w0, w1);
    }
    __syncthreads();
#pragma unroll
    for (int r = 0; r < 4; r++) {
        int n  = n0 + ty + r * 8;
        int kp = kp0 + tx;
        o[eoffO + (size_t)n * K2 + kp] = th[tx][ty + r * 8];
    }
}

// ---------------- cp.async helpers ----------------
__device__ __forceinline__ void cp_async16z(void* dst, const void* src, int sz) {
    u32 d = (u32)__cvta_generic_to_shared(dst);
    asm volatile("cp.async.ca.shared.global [%0], [%1], 16, %2;\n"
                 :: "r"(d), "l"(src), "r"(sz) : "memory");
}
__device__ __forceinline__ void cp_commit() {
    asm volatile("cp.async.commit_group;\n" ::: "memory");
}
template<int N> __device__ __forceinline__ void cp_wait() {
    asm volatile("cp.async.wait_group %0;\n" :: "n"(N) : "memory");
}

// ---------------- mma / ldmatrix ----------------
__device__ __forceinline__ void mma_bf16(float* d, const u32* a, const u32* b) {
    asm volatile(
        "mma.sync.aligned.m16n8k16.row.col.f32.bf16.bf16.f32 "
        "{%0,%1,%2,%3}, {%4,%5,%6,%7}, {%8,%9}, {%0,%1,%2,%3};\n"
        : "+f"(d[0]), "+f"(d[1]), "+f"(d[2]), "+f"(d[3])
        : "r"(a[0]), "r"(a[1]), "r"(a[2]), "r"(a[3]), "r"(b[0]), "r"(b[1]));
}
__device__ __forceinline__ void mma_f16(float* d, const u32* a, const u32* b) {
    asm volatile(
        "mma.sync.aligned.m16n8k16.row.col.f32.f16.f16.f32 "
        "{%0,%1,%2,%3}, {%4,%5,%6,%7}, {%8,%9}, {%0,%1,%2,%3};\n"
        : "+f"(d[0]), "+f"(d[1]), "+f"(d[2]), "+f"(d[3])
        : "r"(a[0]), "r"(a[1]), "r"(a[2]), "r"(a[3]), "r"(b[0]), "r"(b[1]));
}
__device__ __forceinline__ void ldsm_x4(u32& r0, u32& r1, u32& r2, u32& r3, u32 addr) {
    asm volatile("ldmatrix.sync.aligned.m8n8.x4.shared.b16 {%0,%1,%2,%3}, [%4];"
                 : "=r"(r0), "=r"(r1), "=r"(r2), "=r"(r3) : "r"(addr));
}

#define BM 128
#define BN 128
#define KP 16            // k-pairs per tile (32 elements)
#define STR 20           // smem row stride in u32 (16 used + 4 pad)
#define ABUF (128*STR)   // 2560 u32 per array per buffer
#define GEMM_SMEM_BYTES  (8*ABUF*4 + BM*4)
#define GEMMH_SMEM_BYTES (4*ABUF*4 + BM*4)

// ---------------- bf16x2 3-pass GEMM (delta projection) ----------
__global__ __launch_bounds__(256, 1)
void gemm_bf(const u32* __restrict__ Ahi, const u32* __restrict__ Alo,
             const u32* __restrict__ Bhi, const u32* __restrict__ Blo,
             float* __restrict__ C1, const float* __restrict__ bias,
             int M, int Ncols, int K)
{
    extern __shared__ u32 sm[];

    int mblk = blockIdx.y;
    int nblk = blockIdx.x;
    int n0 = nblk * BN;
    int K2 = K / 2;
    int tid = threadIdx.x;

    int crow = tid >> 1;
    int cseg = (tid & 1) * 8;
    size_t abase = (size_t)(mblk * BM + crow) * K2 + cseg;
    size_t bbase = (size_t)(n0 + crow) * K2 + cseg;

    int wid = tid >> 5, lane = tid & 31;
    int g = lane >> 2, tig = lane & 3;
    int wm = wid >> 2, wn = wid & 3;

    u32 aoffL = (u32)((wm * 64 + (lane & 15)) * STR + (lane >> 4) * 4);
    u32 boffL = (u32)((wn * 32 + ((lane >> 4) << 3) + (lane & 7)) * STR + ((lane >> 3) & 1) * 4);

    float acc[4][4][4];
#pragma unroll
    for (int i = 0; i < 4; i++)
#pragma unroll
        for (int j = 0; j < 4; j++)
#pragma unroll
            for (int k = 0; k < 4; k++) acc[i][j][k] = 0.f;

    int KT = K2 / KP;
    int buf = 0;
    u32 sdst = crow * STR + cseg;

    {
        u32* s0 = sm;
        cp_async16z(s0 + 0*ABUF + sdst,     Ahi + abase,     16);
        cp_async16z(s0 + 0*ABUF + sdst + 4, Ahi + abase + 4, 16);
        cp_async16z(s0 + 1*ABUF + sdst,     Alo + abase,     16);
        cp_async16z(s0 + 1*ABUF + sdst + 4, Alo + abase + 4, 16);
        cp_async16z(s0 + 2*ABUF + sdst,     Bhi + bbase,     16);
        cp_async16z(s0 + 2*ABUF + sdst + 4, Bhi + bbase + 4, 16);
        cp_async16z(s0 + 3*ABUF + sdst,     Blo + bbase,     16);
        cp_async16z(s0 + 3*ABUF + sdst + 4, Blo + bbase + 4, 16);
        cp_commit();
    }

    for (int kt = 0; kt < KT; kt++) {
        if (kt + 1 < KT) {
            u32* s1 = sm + (buf ^ 1) * 4 * ABUF;
            size_t ao = abase + (size_t)(kt + 1) * KP;
            size_t bo = bbase + (size_t)(kt + 1) * KP;
            cp_async16z(s1 + 0*ABUF + sdst,     Ahi + ao,     16);
            cp_async16z(s1 + 0*ABUF + sdst + 4, Ahi + ao + 4, 16);
            cp_async16z(s1 + 1*ABUF + sdst,     Alo + ao,     16);
            cp_async16z(s1 + 1*ABUF + sdst + 4, Alo + ao + 4, 16);
            cp_async16z(s1 + 2*ABUF + sdst,     Bhi + bo,     16);
            cp_async16z(s1 + 2*ABUF + sdst + 4, Bhi + bo + 4, 16);
            cp_async16z(s1 + 3*ABUF + sdst,     Blo + bo,     16);
            cp_async16z(s1 + 3*ABUF + sdst + 4, Blo + bo + 4, 16);
            cp_commit();
            cp_wait<1>();
        } else {
            cp_wait<0>();
        }
        __syncthreads();

        u32 aAh = (u32)__cvta_generic_to_shared(sm + buf * 4 * ABUF);
        u32 aAl = aAh + ABUF * 4;
        u32 aBh = aAh + 2 * ABUF * 4;
        u32 aBl = aAh + 3 * ABUF * 4;

#pragma unroll
        for (int ks = 0; ks < 2; ks++) {
            int kb = ks * 8;
            u32 ah[4][4], al[4][4];
#pragma unroll
            for (int mt = 0; mt < 4; mt++) {
                u32 off = (aoffL + mt * 16 * STR + kb) * 4;
                ldsm_x4(ah[mt][0], ah[mt][1], ah[mt][2], ah[mt][3], aAh + off);
                ldsm_x4(al[mt][0], al[mt][1], al[mt][2], al[mt][3], aAl + off);
            }
            u32 bh[4][2], bl[4][2];
#pragma unroll
            for (int np = 0; np < 2; np++) {
                u32 off = (boffL + np * 16 * STR + kb) * 4;
                ldsm_x4(bh[2*np][0], bh[2*np][1], bh[2*np+1][0], bh[2*np+1][1], aBh + off);
                ldsm_x4(bl[2*np][0], bl[2*np][1], bl[2*np+1][0], bl[2*np+1][1], aBl + off);
            }
#pragma unroll
            for (int mt = 0; mt < 4; mt++)
#pragma unroll
                for (int nt = 0; nt < 4; nt++) {
                    mma_bf16(acc[mt][nt], ah[mt], bh[nt]);
                    mma_bf16(acc[mt][nt], ah[mt], bl[nt]);
                    mma_bf16(acc[mt][nt], al[mt], bh[nt]);
                }
        }
        __syncthreads();
        buf ^= 1;
    }

#pragma unroll
    for (int mt = 0; mt < 4; mt++) {
#pragma unroll
        for (int half = 0; half < 2; half++) {
            int gr = mblk * BM + wm * 64 + mt * 16 + g + half * 8;
            float* orow = C1 + (size_t)gr * Ncols;
#pragma unroll
            for (int nt = 0; nt < 4; nt++) {
                int col = n0 + wn * 32 + nt * 8 + tig * 2;
                float v0 = softplusf(acc[mt][nt][half*2+0] + bias[col]);
                float v1 = softplusf(acc[mt][nt][half*2+1] + bias[col+1]);
                *(float2*)(orow + col) = make_float2(v0, v1);
            }
        }
    }
}

// ---------------- fp16 single-pass GEMM (MoE up/down) ----------
// MODE 1: A gathered via rowidx, dual B/C (nblk<16 -> B1/C1, else B2/C2)
// MODE 2: A compact rows; C1[rowidx[r],:] += acc (scatter)
template<int MODE>
__global__ __launch_bounds__(256, 1)
void gemm_hf(const u32* __restrict__ A,
             const u32* __restrict__ B1, const u32* __restrict__ B2,
             float* __restrict__ C1, float* __restrict__ C2,
             int Ncols, int K,
             const int* __restrict__ rowidx, const int* __restrict__ cntp)
{
    extern __shared__ u32 sm[];
    int* sidx = (int*)(sm + 4 * ABUF);

    int M = *cntp;
    int mblk = blockIdx.y;
    if (mblk * BM >= M) return;
    int nblk = blockIdx.x;

    const u32* Bp = B1;
    float* Cout = C1;
    int nb = nblk;
    if (MODE == 1 && nblk >= 16) { Bp = B2; Cout = C2; nb = nblk - 16; }
    int n0 = nb * BN;
    int K2 = K / 2;
    int tid = threadIdx.x;

    for (int i = tid; i < BM; i += 256) {
        int gr = mblk * BM + i;
        sidx[i] = (gr < M) ? rowidx[gr] : -1;
    }
    __syncthreads();

    int crow = tid >> 1;
    int cseg = (tid & 1) * 8;
    int asz;
    size_t abase;
    if (MODE == 1) {
        int s = sidx[crow];
        asz = (s >= 0) ? 16 : 0;
        abase = (size_t)(s >= 0 ? s : 0) * K2 + cseg;
    } else {
        int gr = mblk * BM + crow;
        asz = (gr < M) ? 16 : 0;
        abase = (size_t)(gr < M ? gr : 0) * K2 + cseg;
    }
    size_t bbase = (size_t)(n0 + crow) * K2 + cseg;

    int wid = tid >> 5, lane = tid & 31;
    int g = lane >> 2, tig = lane & 3;
    int wm = wid >> 2, wn = wid & 3;

    u32 aoffL = (u32)((wm * 64 + (lane & 15)) * STR + (lane >> 4) * 4);
    u32 boffL = (u32)((wn * 32 + ((lane >> 4) << 3) + (lane & 7)) * STR + ((lane >> 3) & 1) * 4);

    float acc[4][4][4];
#pragma unroll
    for (int i = 0; i < 4; i++)
#pragma unroll
        for (int j = 0; j < 4; j++)
#pragma unroll
            for (int k = 0; k < 4; k++) acc[i][j][k] = 0.f;

    int KT = K2 / KP;
    int buf = 0;
    u32 sdst = crow * STR + cseg;

    {
        u32* s0 = sm;
        cp_async16z(s0 + 0*ABUF + sdst,     A + abase,      asz);
        cp_async16z(s0 + 0*ABUF + sdst + 4, A + abase + 4,  asz);
        cp_async16z(s0 + 1*ABUF + sdst,     Bp + bbase,     16);
        cp_async16z(s0 + 1*ABUF + sdst + 4, Bp + bbase + 4, 16);
        cp_commit();
    }

    for (int kt = 0; kt < KT; kt++) {
        if (kt + 1 < KT) {
            u32* s1 = sm + (buf ^ 1) * 2 * ABUF;
            size_t ao = abase + (size_t)(kt + 1) * KP;
            size_t bo = bbase + (size_t)(kt + 1) * KP;
            cp_async16z(s1 + 0*ABUF + sdst,     A + ao,      asz);
            cp_async16z(s1 + 0*ABUF + sdst + 4, A + ao + 4,  asz);
            cp_async16z(s1 + 1*ABUF + sdst,     Bp + bo,     16);
            cp_async16z(s1 + 1*ABUF + sdst + 4, Bp + bo + 4, 16);
            cp_commit();
            cp_wait<1>();
        } else {
            cp_wait<0>();
        }
        __syncthreads();

        u32 aA = (u32)__cvta_generic_to_shared(sm + buf * 2 * ABUF);
        u32 aB = aA + ABUF * 4;

#pragma unroll
        for (int ks = 0; ks < 2; ks++) {
            int kb = ks * 8;
            u32 ah[4][4];
#pragma unroll
            for (int mt = 0; mt < 4; mt++) {
                u32 off = (aoffL + mt * 16 * STR + kb) * 4;
                ldsm_x4(ah[mt][0], ah[mt][1], ah[mt][2], ah[mt][3], aA + off);
            }
            u32 bh[4][2];
#pragma unroll
            for (int np = 0; np < 2; np++) {
                u32 off = (boffL + np * 16 * STR + kb) * 4;
                ldsm_x4(bh[2*np][0], bh[2*np][1], bh[2*np+1][0], bh[2*np+1][1], aB + off);
            }
#pragma unroll
            for (int mt = 0; mt < 4; mt++)
#pragma unroll
                for (int nt = 0; nt < 4; nt++)
                    mma_f16(acc[mt][nt], ah[mt], bh[nt]);
        }
        __syncthreads();
        buf ^= 1;
    }

#pragma unroll
    for (int mt = 0; mt < 4; mt++) {
#pragma unroll
        for (int half = 0; half < 2; half++) {
            int lr = wm * 64 + mt * 16 + g + half * 8;
            int gr = mblk * BM + lr;
            if (gr >= M) continue;
            float* orow;
            if (MODE == 2) {
                int tok = sidx[lr];
                orow = C1 + (size_t)tok * Ncols;
            } else {
                orow = Cout + (size_t)gr * Ncols;
            }
#pragma unroll
            for (int nt = 0; nt < 4; nt++) {
                int col = n0 + wn * 32 + nt * 8 + tig * 2;
                float v0 = acc[mt][nt][half * 2 + 0];
                float v1 = acc[mt][nt][half * 2 + 1];
                if (MODE == 1) {
                    *(float2*)(orow + col) = make_float2(v0, v1);
                } else {
                    float2 old = *(float2*)(orow + col);
                    old.x += v0; old.y += v1;
                    *(float2*)(orow + col) = old;
                }
            }
        }
    }
}

// ---------------- small projections: Bm, Cm (from x) ----------------
__global__ __launch_bounds__(128)
void proj_small(const float* __restrict__ x, const float* __restrict__ WB,
                const float* __restrict__ WC)
{
    int n = blockIdx.x;
    __shared__ float xs[DD];
    const float* xr = x + (size_t)n * DD;
    for (int i = threadIdx.x; i < DD; i += 128) xs[i] = xr[i];
    __syncthreads();
    int warp = threadIdx.x >> 5, lane = threadIdx.x & 31;
    for (int c = warp; c < 32; c += 4) {
        const float* W; int col; float* out;
        if (c < 16) { W = WB; col = c;      out = g_Bm + (size_t)n * SS + col; }
        else        { W = WC; col = c - 16; out = g_Cm + (size_t)n * SS + col; }
        float s = 0.f;
        for (int k = lane; k < DD; k += 32)
            s = fmaf(xs[k], W[(size_t)k * SS + col], s);
        s += __shfl_xor_sync(~0u, s, 16);
        s += __shfl_xor_sync(~0u, s, 8);
        s += __shfl_xor_sync(~0u, s, 4);
        s += __shfl_xor_sync(~0u, s, 2);
        s += __shfl_xor_sync(~0u, s, 1);
        if (lane == 0) *out = s;
    }
}

// ---------------- selective scan (register partials + smem reduce) -------------
__global__ __launch_bounds__(256)
void scan_kernel(const float* __restrict__ x, const float* __restrict__ A_log,
                 const float* __restrict__ D_param)
{
    int b = blockIdx.x >> 6;
    int dchunk = blockIdx.x & 63;
    int dl = threadIdx.x >> 4;      // d-local 0..15
    int s  = threadIdx.x & 15;      // state index
    int d = dchunk * 16 + dl;

    float A_ds = -__expf(A_log[d * SS + s]);

    __shared__ float sx[16][16], sd[16][16];
    __shared__ float sB[16][17], sC[16][17];
    __shared__ float sp[16 * 272];  // [q][s*17 + dl]
    __shared__ float sDp[16];

    int tt = threadIdx.x >> 4;
    int cc = threadIdx.x & 15;
    const int base_bt = b * LL;

    if (threadIdx.x < 16) sDp[threadIdx.x] = D_param[dchunk * 16 + threadIdx.x];

    size_t xoff = ((size_t)(base_bt + tt)) * DD + dchunk * 16 + cc;
    float rx = x[xoff];
    float rd = g_delta[xoff];
    size_t boff = ((size_t)(base_bt + tt)) * SS + cc;
    float rB = g_Bm[boff];
    float rC = g_Cm[boff];

    float h = 0.f;
    for (int t0 = 0; t0 < LL; t0 += 16) {
        __syncthreads();
        sx[tt][cc] = rx; sd[tt][cc] = rd; sB[tt][cc] = rB; sC[tt][cc] = rC;
        __syncthreads();
        if (t0 + 16 < LL) {
            size_t xo = ((size_t)(base_bt + t0 + 16 + tt)) * DD + dchunk * 16 + cc;
            rx = x[xo]; rd = g_delta[xo];
            size_t bo = ((size_t)(base_bt + t0 + 16 + tt)) * SS + cc;
            rB = g_Bm[bo]; rC = g_Cm[bo];
        }
        float p[16];
#pragma unroll
        for (int q = 0; q < 16; q++) {
            float xv = sx[q][dl], dv = sd[q][dl];
            float Bv = sB[q][s],  Cv = sC[q][s];
            float a  = __expf(fminf(dv * A_ds, 10.f));
            float bBc = fminf(fmaxf(dv * Bv, -10.f), 10.f);
            h = fminf(fmaxf(a * h + bBc * xv, -10000.f), 10000.f);
            p[q] = h * Cv;
        }
#pragma unroll
        for (int q = 0; q < 16; q++)
            sp[q * 272 + s * 17 + dl] = p[q];
        __syncthreads();
        // reduction role: (q2 = tt, d2 = cc)
        float ysum = 0.f;
#pragma unroll
        for (int s2 = 0; s2 < 16; s2++)
            ysum += sp[tt * 272 + s2 * 17 + cc];
        float y = fmaf(sx[tt][cc], sDp[cc], ysum);
        size_t yo = ((size_t)(base_bt + t0 + tt)) * DD + dchunk * 16 + cc;
        g_ssm[yo] = y;
        g_acc[yo] = y;
        float yn = __shfl_down_sync(~0u, y, 1);
        if (!(cc & 1)) {
            float ya = fminf(fmaxf(y,  -60000.f), 60000.f);
            float yb = fminf(fmaxf(yn, -60000.f), 60000.f);
            size_t po = ((size_t)(base_bt + t0 + tt)) * (DD/2) + dchunk * 8 + (cc >> 1);
            g_sF[po] = pack_h2(ya, yb);
        }
    }
}

// ---------------- router on SSM output: softmax, top-2, expert lists ----------
__global__ __launch_bounds__(128)
void router_kernel(const float* __restrict__ WR)
{
    int n = blockIdx.x;
    __shared__ float xs[DD];
    __shared__ float logits[EE];
    const float* xr = g_ssm + (size_t)n * DD;
    for (int i = threadIdx.x; i < DD; i += 128) xs[i] = xr[i];
    __syncthreads();
    int warp = threadIdx.x >> 5, lane = threadIdx.x & 31;
    {
        float s = 0.f;
        for (int k = lane; k < DD; k += 32)
            s = fmaf(xs[k], WR[(size_t)k * EE + warp], s);
        s += __shfl_xor_sync(~0u, s, 16);
        s += __shfl_xor_sync(~0u, s, 8);
        s += __shfl_xor_sync(~0u, s, 4);
        s += __shfl_xor_sync(~0u, s, 2);
        s += __shfl_xor_sync(~0u, s, 1);
        if (lane == 0) logits[warp] = s;
    }
    __syncthreads();
    if (threadIdx.x == 0) {
        float l[4] = {logits[0], logits[1], logits[2], logits[3]};
        float m = fmaxf(fmaxf(l[0], l[1]), fmaxf(l[2], l[3]));
        float e[4], sum = 0.f;
#pragma unroll
        for (int i = 0; i < 4; i++) { e[i] = __expf(l[i] - m); sum += e[i]; }
        float p[4];
#pragma unroll
        for (int i = 0; i < 4; i++) p[i] = e[i] / sum;
        int i0 = 0;
#pragma unroll
        for (int i = 1; i < 4; i++) if (p[i] > p[i0]) i0 = i;
        int i1 = -1;
#pragma unroll
        for (int i = 0; i < 4; i++) {
            if (i == i0) continue;
            if (i1 < 0 || p[i] > p[i1]) i1 = i;
        }
        float w0 = p[i0], w1 = p[i1];
        float sw = w0 + w1 + 1e-9f;
        w0 /= sw; w1 /= sw;
        int pos = atomicAdd(&g_cnt[i0], 1);
        g_list[i0*NN + pos] = n; g_cw[i0*NN + pos] = w0;
        pos = atomicAdd(&g_cnt[i1], 1);
        g_list[i1*NN + pos] = n; g_cw[i1*NN + pos] = w1;
    }
}

// ---------------- silu(G)*U -> rmsnorm(wn) -> * cw (fp16 output) --------------
__global__ __launch_bounds__(256)
void act_norm(const float* __restrict__ wn, const float* __restrict__ cw,
              const int* __restrict__ cntp)
{
    int i = blockIdx.x;
    if (i >= *cntp) return;
    __shared__ float buf[HH];
    __shared__ float red[8];
    float ss = 0.f;
    for (int j = threadIdx.x; j < HH; j += 256) {
        float g = g_G[(size_t)i * HH + j];
        float u = g_U[(size_t)i * HH + j];
        float v = (g / (1.f + __expf(-g))) * u;
        buf[j] = v;
        ss = fmaf(v, v, ss);
    }
    ss += __shfl_xor_sync(~0u, ss, 16);
    ss += __shfl_xor_sync(~0u, ss, 8);
    ss += __shfl_xor_sync(~0u, ss, 4);
    ss += __shfl_xor_sync(~0u, ss, 2);
    ss += __shfl_xor_sync(~0u, ss, 1);
    if ((threadIdx.x & 31) == 0) red[threadIdx.x >> 5] = ss;
    __syncthreads();
    if (threadIdx.x < 32) {
        float v = (threadIdx.x < 8) ? red[threadIdx.x] : 0.f;
        v += __shfl_xor_sync(~0u, v, 4);
        v += __shfl_xor_sync(~0u, v, 2);
        v += __shfl_xor_sync(~0u, v, 1);
        if (threadIdx.x == 0) red[0] = v;
    }
    __syncthreads();
    float scale = cw[i] * rsqrtf(red[0] / (float)HH + 1e-6f);
    for (int j2 = threadIdx.x; j2 < HH / 2; j2 += 256) {
        float v0 = wn[2 * j2]     * buf[2 * j2]     * scale;
        float v1 = wn[2 * j2 + 1] * buf[2 * j2 + 1] * scale;
        g_aF[(size_t)i * (HH/2) + j2] = pack_h2(v0, v1);
    }
}

// ---------------- final rmsnorm over (ssm + moe) ----------------
__global__ __launch_bounds__(256)
void final_norm(const float* __restrict__ norm_w, float* __restrict__ out)
{
    int n = blockIdx.x;
    __shared__ float red[8];
    float ss = 0.f;
    const float* row = g_acc + (size_t)n * DD;
    for (int j = threadIdx.x; j < DD; j += 256) {
        float v = row[j];
        ss = fmaf(v, v, ss);
    }
    ss += __shfl_xor_sync(~0u, ss, 16);
    ss += __shfl_xor_sync(~0u, ss, 8);
    ss += __shfl_xor_sync(~0u, ss, 4);
    ss += __shfl_xor_sync(~0u, ss, 2);
    ss += __shfl_xor_sync(~0u, ss, 1);
    if ((threadIdx.x & 31) == 0) red[threadIdx.x >> 5] = ss;
    __syncthreads();
    if (threadIdx.x < 32) {
        float v = (threadIdx.x < 8) ? red[threadIdx.x] : 0.f;
        v += __shfl_xor_sync(~0u, v, 4);
        v += __shfl_xor_sync(~0u, v, 2);
        v += __shfl_xor_sync(~0u, v, 1);
        if (threadIdx.x == 0) red[0] = v;
    }
    __syncthreads();
    float inv = rsqrtf(red[0] / (float)DD + 1e-6f);
    for (int j = threadIdx.x; j < DD; j += 256)
        out[(size_t)n * DD + j] = norm_w[j] * row[j] * inv;
}

// ---------------- launch ----------------
extern "C" void kernel_launch(void* const* d_in, const int* in_sizes, int n_in,
                              void* d_out, int out_size)
{
    const float* x        = (const float*)d_in[0];
    const float* A_log    = (const float*)d_in[1];
    const float* D_param  = (const float*)d_in[2];
    const float* W_delta  = (const float*)d_in[3];
    const float* b_delta  = (const float*)d_in[4];
    const float* W_B      = (const float*)d_in[5];
    const float* W_C      = (const float*)d_in[6];
    const float* W_router = (const float*)d_in[7];
    const float* Wg       = (const float*)d_in[8];
    const float* Wu       = (const float*)d_in[9];
    const float* Wd       = (const float*)d_in[10];
    const float* wn_exp   = (const float*)d_in[11];
    const float* norm_w   = (const float*)d_in[12];
    float* out = (float*)d_out;

    float *p_delta, *p_G, *p_U, *p_acc, *p_cw;
    int *p_cnt, *p_list;
    u32 *p_xHi, *p_xLo, *p_sF, *p_aF;
    u32 *p_WdHi, *p_WdLo, *p_WgF, *p_WuF, *p_WnF;
    cudaGetSymbolAddress((void**)&p_delta, g_delta);
    cudaGetSymbolAddress((void**)&p_G,     g_G);
    cudaGetSymbolAddress((void**)&p_U,     g_U);
    cudaGetSymbolAddress((void**)&p_acc,   g_acc);
    cudaGetSymbolAddress((void**)&p_cnt,   g_cnt);
    cudaGetSymbolAddress((void**)&p_list,  g_list);
    cudaGetSymbolAddress((void**)&p_cw,    g_cw);
    cudaGetSymbolAddress((void**)&p_xHi,   g_xHi);
    cudaGetSymbolAddress((void**)&p_xLo,   g_xLo);
    cudaGetSymbolAddress((void**)&p_sF,    g_sF);
    cudaGetSymbolAddress((void**)&p_aF,    g_aF);
    cudaGetSymbolAddress((void**)&p_WdHi,  g_WdHi);
    cudaGetSymbolAddress((void**)&p_WdLo,  g_WdLo);
    cudaGetSymbolAddress((void**)&p_WgF,   g_WgF);
    cudaGetSymbolAddress((void**)&p_WuF,   g_WuF);
    cudaGetSymbolAddress((void**)&p_WnF,   g_WnF);

    cudaFuncSetAttribute(gemm_bf,    cudaFuncAttributeMaxDynamicSharedMemorySize, GEMM_SMEM_BYTES);
    cudaFuncSetAttribute(gemm_hf<1>, cudaFuncAttributeMaxDynamicSharedMemorySize, GEMMH_SMEM_BYTES);
    cudaFuncSetAttribute(gemm_hf<2>, cudaFuncAttributeMaxDynamicSharedMemorySize, GEMMH_SMEM_BYTES);

    zero_counts<<<1, 32>>>();

    // operand pre-conversion
    {
        int n2 = NN * DD / 2;
        split_x_kernel<<<(n2 + 255) / 256, 256>>>(x, p_xHi, p_xLo, n2);
    }
    {
        dim3 blk(32, 8);
        dim3 gWdel(DD/2/32, DD/32, 1);
        split_w_kernel<<<gWdel, blk>>>(W_delta, p_WdHi, p_WdLo, DD, DD);
        dim3 gUp(DD/2/32, HH/32, EE);
        split_w_h_kernel<<<gUp, blk>>>(Wg, p_WgF, DD, HH);
        split_w_h_kernel<<<gUp, blk>>>(Wu, p_WuF, DD, HH);
        dim3 gDn(HH/2/32, DD/32, EE);
        split_w_h_kernel<<<gDn, blk>>>(Wd, p_WnF, HH, DD);
    }

    // delta = softplus(x @ W_delta + b)   [bf16x2 3-pass]
    {
        dim3 grid(DD / BN, NN / BM);
        gemm_bf<<<grid, 256, GEMM_SMEM_BYTES>>>(
            p_xHi, p_xLo, p_WdHi, p_WdLo, p_delta, b_delta, NN, DD, DD);
    }

    // Bm, Cm from x
    proj_small<<<NN, 128>>>(x, W_B, W_C);

    // selective scan -> g_ssm / g_acc / fp16 ssm
    scan_kernel<<<BB * (DD / 16), 256>>>(x, A_log, D_param);

    // router on SSM output
    router_kernel<<<NN, 128>>>(W_router);

    // experts
    for (int e = 0; e < EE; e++) {
        const u32* WgF_e = p_WgF + (size_t)e * HH * (DD/2);
        const u32* WuF_e = p_WuF + (size_t)e * HH * (DD/2);
        const u32* WnF_e = p_WnF + (size_t)e * DD * (HH/2);
        const float* wn_e = wn_exp + (size_t)e * HH;
        const int* rowidx = p_list + (size_t)e * NN;
        const int* cntp   = p_cnt + e;
        const float* cwp  = p_cw + (size_t)e * NN;

        // G = gather(ssm) @ Wg_e ; U = gather(ssm) @ Wu_e  [fp16 single-pass]
        {
            dim3 grid(2 * HH / BN, NN / BM);   // nblk<16 -> G, else U
            gemm_hf<1><<<grid, 256, GEMMH_SMEM_BYTES>>>(
                p_sF, WgF_e, WuF_e, p_G, p_U, HH, DD, rowidx, cntp);
        }
        // act = wn * rmsnorm(silu(G)*U) * cw  (fp16 output)
        act_norm<<<NN, 256>>>(wn_e, cwp, cntp);
        // acc[token] += act @ Wd_e  [fp16 single-pass]
        {
            dim3 grid(DD / BN, NN / BM);
            gemm_hf<2><<<grid, 256, GEMMH_SMEM_BYTES>>>(
                p_aF, WnF_e, nullptr, p_acc, nullptr, DD, HH, rowidx, cntp);
        }
    }

    // out = rmsnorm(ssm + moe, norm_w)
    final_norm<<<NN, 256>>>(norm_w, out);
}

// round 10
// speedup vs baseline: 4.0475x; 1.1906x over previous
#include <cuda_runtime.h>
#include <cuda_bf16.h>
#include <cuda_fp16.h>
#include <math.h>
#include <stdint.h>

// Problem dims (fixed)
#define BB 2
#define LL 2048
#define DD 1024
#define SS 16
#define EE 4
#define HH 2048
#define NN (BB*LL)   // 4096

typedef uint32_t u32;

// ---------------- scratch (device globals; no allocation allowed) ----------------
__device__ float g_delta[NN*DD];
__device__ float g_Bm[NN*SS];
__device__ float g_Cm[NN*SS];
__device__ float g_ssm[NN*DD];
__device__ int   g_cnt[EE];
__device__ int   g_list[EE*NN];
__device__ float g_cw[EE*NN];
__device__ int   g_loc[2*NN];            // token -> (e*NN + pos), two entries
__device__ float g_G[(size_t)EE*NN*HH];  // per-expert compact
__device__ float g_U[(size_t)EE*NN*HH];
__device__ float g_Dn[(size_t)EE*NN*DD]; // per-expert compact down output

// bf16x2 split operands for delta GEMM (packed: low16 = even k, high16 = odd k)
__device__ u32 g_xHi[NN*DD/2],   g_xLo[NN*DD/2];      // x           [NN][512]
__device__ u32 g_WdHi[DD*DD/2],  g_WdLo[DD*DD/2];     // W_delta^T   [D][512]
// fp16 single-precision MoE operands (pair-packed)
__device__ u32 g_sF[NN*DD/2];                         // ssm  (fp16 pairs)
__device__ u32 g_aF[(size_t)EE*NN*HH/2];              // act  (fp16 pairs, per-expert)
__device__ u32 g_WgF[EE*HH*DD/2];                     // Wg^T  [e][H][512]
__device__ u32 g_WuF[EE*HH*DD/2];                     // Wu^T  [e][H][512]
__device__ u32 g_WnF[EE*DD*HH/2];                     // Wd^T  [e][D][1024]

__device__ __forceinline__ float softplusf(float z) {
    return (z > 20.f) ? z : log1pf(__expf(z));
}

__device__ __forceinline__ void split2(float a, float b, u32& hi, u32& lo) {
    __nv_bfloat16 ah = __float2bfloat16(a);
    __nv_bfloat16 bh = __float2bfloat16(b);
    float ra = a - __bfloat162float(ah);
    float rb = b - __bfloat162float(bh);
    __nv_bfloat16 al = __float2bfloat16(ra);
    __nv_bfloat16 bl = __float2bfloat16(rb);
    hi = ((u32)__bfloat16_as_ushort(bh) << 16) | __bfloat16_as_ushort(ah);
    lo = ((u32)__bfloat16_as_ushort(bl) << 16) | __bfloat16_as_ushort(al);
}

__device__ __forceinline__ u32 pack_h2(float a, float b) {
    __half2 h = __floats2half2_rn(a, b);
    return *reinterpret_cast<u32*>(&h);
}

// ---------------- zero counts ----------------
__global__ void zero_counts() {
    if (threadIdx.x < EE) g_cnt[threadIdx.x] = 0;
}

// ---------------- split x (bf16 pairs, row-major) ----------------
__global__ __launch_bounds__(256)
void split_x_kernel(const float* __restrict__ in, u32* __restrict__ oh,
                    u32* __restrict__ ol, int n2) {
    int i = blockIdx.x * blockDim.x + threadIdx.x;
    if (i < n2) {
        float2 v = ((const float2*)in)[i];
        u32 hi, lo; split2(v.x, v.y, hi, lo);
        oh[i] = hi; ol[i] = lo;
    }
}

// ---------------- split + transpose W_delta (bf16 pairs) ----------------
__global__ __launch_bounds__(256)
void split_w_kernel(const float* __restrict__ W, u32* __restrict__ oh,
                    u32* __restrict__ ol, int K, int N) {
    int K2 = K / 2;
    __shared__ u32 th[32][33], tl[32][33];
    int kp0 = blockIdx.x * 32, n0 = blockIdx.y * 32;
    int tx = threadIdx.x, ty = threadIdx.y;
#pragma unroll
    for (int r = 0; r < 4; r++) {
        int kp = kp0 + ty + r * 8;
        int n  = n0 + tx;
        float w0 = W[(size_t)(2 * kp) * N + n];
        float w1 = W[(size_t)(2 * kp + 1) * N + n];
        u32 hi, lo; split2(w0, w1, hi, lo);
        th[ty + r * 8][tx] = hi;
        tl[ty + r * 8][tx] = lo;
    }
    __syncthreads();
#pragma unroll
    for (int r = 0; r < 4; r++) {
        int n  = n0 + ty + r * 8;
        int kp = kp0 + tx;
        oh[(size_t)n * K2 + kp] = th[tx][ty + r * 8];
        ol[(size_t)n * K2 + kp] = tl[tx][ty + r * 8];
    }
}

// ---------------- convert + transpose MoE weight (single fp16 pairs) ----------
__global__ __launch_bounds__(256)
void split_w_h_kernel(const float* __restrict__ W, u32* __restrict__ o,
                      int K, int N) {
    int K2 = K / 2;
    size_t eoffW = (size_t)blockIdx.z * K * N;
    size_t eoffO = (size_t)blockIdx.z * N * K2;
    __shared__ u32 th[32][33];
    int kp0 = blockIdx.x * 32, n0 = blockIdx.y * 32;
    int tx = threadIdx.x, ty = threadIdx.y;
#pragma unroll
    for (int r = 0; r < 4; r++) {
        int kp = kp0 + ty + r * 8;
        int n  = n0 + tx;
        float w0 = W[eoffW + (size_t)(2 * kp) * N + n];
        float w1 = W[eoffW + (size_t)(2 * kp + 1) * N + n];
        th[ty + r * 8][tx] = pack_h2(w0, w1);
    }
    __syncthreads();
#pragma unroll
    for (int r = 0; r < 4; r++) {
        int n  = n0 + ty + r * 8;
        int kp = kp0 + tx;
        o[eoffO + (size_t)n * K2 + kp] = th[tx][ty + r * 8];
    }
}

// ---------------- cp.async helpers ----------------
__device__ __forceinline__ void cp_async16z(void* dst, const void* src, int sz) {
    u32 d = (u32)__cvta_generic_to_shared(dst);
    asm volatile("cp.async.ca.shared.global [%0], [%1], 16, %2;\n"
                 :: "r"(d), "l"(src), "r"(sz) : "memory");
}
__device__ __forceinline__ void cp_commit() {
    asm volatile("cp.async.commit_group;\n" ::: "memory");
}
template<int N> __device__ __forceinline__ void cp_wait() {
    asm volatile("cp.async.wait_group %0;\n" :: "n"(N) : "memory");
}

// ---------------- mma / ldmatrix ----------------
__device__ __forceinline__ void mma_bf16(float* d, const u32* a, const u32* b) {
    asm volatile(
        "mma.sync.aligned.m16n8k16.row.col.f32.bf16.bf16.f32 "
        "{%0,%1,%2,%3}, {%4,%5,%6,%7}, {%8,%9}, {%0,%1,%2,%3};\n"
        : "+f"(d[0]), "+f"(d[1]), "+f"(d[2]), "+f"(d[3])
        : "r"(a[0]), "r"(a[1]), "r"(a[2]), "r"(a[3]), "r"(b[0]), "r"(b[1]));
}
__device__ __forceinline__ void mma_f16(float* d, const u32* a, const u32* b) {
    asm volatile(
        "mma.sync.aligned.m16n8k16.row.col.f32.f16.f16.f32 "
        "{%0,%1,%2,%3}, {%4,%5,%6,%7}, {%8,%9}, {%0,%1,%2,%3};\n"
        : "+f"(d[0]), "+f"(d[1]), "+f"(d[2]), "+f"(d[3])
        : "r"(a[0]), "r"(a[1]), "r"(a[2]), "r"(a[3]), "r"(b[0]), "r"(b[1]));
}
__device__ __forceinline__ void ldsm_x4(u32& r0, u32& r1, u32& r2, u32& r3, u32 addr) {
    asm volatile("ldmatrix.sync.aligned.m8n8.x4.shared.b16 {%0,%1,%2,%3}, [%4];"
                 : "=r"(r0), "=r"(r1), "=r"(r2), "=r"(r3) : "r"(addr));
}

#define BM 128
#define BN 128
#define KP 16            // k-pairs per tile (32 elements)
#define STR 20           // smem row stride in u32 (16 used + 4 pad)
#define ABUF (128*STR)   // 2560 u32 per array per buffer
#define GEMM_SMEM_BYTES  (8*ABUF*4 + BM*4)
#define GEMMH_SMEM_BYTES (4*ABUF*4 + BM*4)

// ---------------- bf16x2 3-pass GEMM (delta projection) ----------
__global__ __launch_bounds__(256, 1)
void gemm_bf(const u32* __restrict__ Ahi, const u32* __restrict__ Alo,
             const u32* __restrict__ Bhi, const u32* __restrict__ Blo,
             float* __restrict__ C1, const float* __restrict__ bias,
             int M, int Ncols, int K)
{
    extern __shared__ u32 sm[];

    int mblk = blockIdx.y;
    int nblk = blockIdx.x;
    int n0 = nblk * BN;
    int K2 = K / 2;
    int tid = threadIdx.x;

    int crow = tid >> 1;
    int cseg = (tid & 1) * 8;
    size_t abase = (size_t)(mblk * BM + crow) * K2 + cseg;
    size_t bbase = (size_t)(n0 + crow) * K2 + cseg;

    int wid = tid >> 5, lane = tid & 31;
    int g = lane >> 2, tig = lane & 3;
    int wm = wid >> 2, wn = wid & 3;

    u32 aoffL = (u32)((wm * 64 + (lane & 15)) * STR + (lane >> 4) * 4);
    u32 boffL = (u32)((wn * 32 + ((lane >> 4) << 3) + (lane & 7)) * STR + ((lane >> 3) & 1) * 4);

    float acc[4][4][4];
#pragma unroll
    for (int i = 0; i < 4; i++)
#pragma unroll
        for (int j = 0; j < 4; j++)
#pragma unroll
            for (int k = 0; k < 4; k++) acc[i][j][k] = 0.f;

    int KT = K2 / KP;
    int buf = 0;
    u32 sdst = crow * STR + cseg;

    {
        u32* s0 = sm;
        cp_async16z(s0 + 0*ABUF + sdst,     Ahi + abase,     16);
        cp_async16z(s0 + 0*ABUF + sdst + 4, Ahi + abase + 4, 16);
        cp_async16z(s0 + 1*ABUF + sdst,     Alo + abase,     16);
        cp_async16z(s0 + 1*ABUF + sdst + 4, Alo + abase + 4, 16);
        cp_async16z(s0 + 2*ABUF + sdst,     Bhi + bbase,     16);
        cp_async16z(s0 + 2*ABUF + sdst + 4, Bhi + bbase + 4, 16);
        cp_async16z(s0 + 3*ABUF + sdst,     Blo + bbase,     16);
        cp_async16z(s0 + 3*ABUF + sdst + 4, Blo + bbase + 4, 16);
        cp_commit();
    }

    for (int kt = 0; kt < KT; kt++) {
        if (kt + 1 < KT) {
            u32* s1 = sm + (buf ^ 1) * 4 * ABUF;
            size_t ao = abase + (size_t)(kt + 1) * KP;
            size_t bo = bbase + (size_t)(kt + 1) * KP;
            cp_async16z(s1 + 0*ABUF + sdst,     Ahi + ao,     16);
            cp_async16z(s1 + 0*ABUF + sdst + 4, Ahi + ao + 4, 16);
            cp_async16z(s1 + 1*ABUF + sdst,     Alo + ao,     16);
            cp_async16z(s1 + 1*ABUF + sdst + 4, Alo + ao + 4, 16);
            cp_async16z(s1 + 2*ABUF + sdst,     Bhi + bo,     16);
            cp_async16z(s1 + 2*ABUF + sdst + 4, Bhi + bo + 4, 16);
            cp_async16z(s1 + 3*ABUF + sdst,     Blo + bo,     16);
            cp_async16z(s1 + 3*ABUF + sdst + 4, Blo + bo + 4, 16);
            cp_commit();
            cp_wait<1>();
        } else {
            cp_wait<0>();
        }
        __syncthreads();

        u32 aAh = (u32)__cvta_generic_to_shared(sm + buf * 4 * ABUF);
        u32 aAl = aAh + ABUF * 4;
        u32 aBh = aAh + 2 * ABUF * 4;
        u32 aBl = aAh + 3 * ABUF * 4;

#pragma unroll
        for (int ks = 0; ks < 2; ks++) {
            int kb = ks * 8;
            u32 ah[4][4], al[4][4];
#pragma unroll
            for (int mt = 0; mt < 4; mt++) {
                u32 off = (aoffL + mt * 16 * STR + kb) * 4;
                ldsm_x4(ah[mt][0], ah[mt][1], ah[mt][2], ah[mt][3], aAh + off);
                ldsm_x4(al[mt][0], al[mt][1], al[mt][2], al[mt][3], aAl + off);
            }
            u32 bh[4][2], bl[4][2];
#pragma unroll
            for (int np = 0; np < 2; np++) {
                u32 off = (boffL + np * 16 * STR + kb) * 4;
                ldsm_x4(bh[2*np][0], bh[2*np][1], bh[2*np+1][0], bh[2*np+1][1], aBh + off);
                ldsm_x4(bl[2*np][0], bl[2*np][1], bl[2*np+1][0], bl[2*np+1][1], aBl + off);
            }
#pragma unroll
            for (int mt = 0; mt < 4; mt++)
#pragma unroll
                for (int nt = 0; nt < 4; nt++) {
                    mma_bf16(acc[mt][nt], ah[mt], bh[nt]);
                    mma_bf16(acc[mt][nt], ah[mt], bl[nt]);
                    mma_bf16(acc[mt][nt], al[mt], bh[nt]);
                }
        }
        __syncthreads();
        buf ^= 1;
    }

#pragma unroll
    for (int mt = 0; mt < 4; mt++) {
#pragma unroll
        for (int half = 0; half < 2; half++) {
            int gr = mblk * BM + wm * 64 + mt * 16 + g + half * 8;
            float* orow = C1 + (size_t)gr * Ncols;
#pragma unroll
            for (int nt = 0; nt < 4; nt++) {
                int col = n0 + wn * 32 + nt * 8 + tig * 2;
                float v0 = softplusf(acc[mt][nt][half*2+0] + bias[col]);
                float v1 = softplusf(acc[mt][nt][half*2+1] + bias[col+1]);
                *(float2*)(orow + col) = make_float2(v0, v1);
            }
        }
    }
}

// ---------------- fp16 single-pass GEMM (MoE up/down), expert-batched ----------
// blockIdx.z = expert.
// MODE 1: A (g_sF) gathered via rowidx, dual B/C (nblk<16 -> B1/C1 (G), else B2/C2 (U));
//         outputs at compact row (e*NN + gr).
// MODE 2: A compact per-expert rows (Abase + e*NN*K2); C1[(e*NN+gr),:] = acc (plain store)
template<int MODE>
__global__ __launch_bounds__(256, 2)
void gemm_hf(const u32* __restrict__ A,
             const u32* __restrict__ B1, const u32* __restrict__ B2,
             float* __restrict__ C1, float* __restrict__ C2,
             int Ncols, int K)
{
    extern __shared__ u32 sm[];
    int* sidx = (int*)(sm + 4 * ABUF);

    int e = blockIdx.z;
    int M = g_cnt[e];
    int mblk = blockIdx.y;
    if (mblk * BM >= M) return;
    int nblk = blockIdx.x;
    int K2 = K / 2;

    const u32* Bp = B1 + (size_t)e * Ncols * K2;
    float* Cout = C1;
    int nb = nblk;
    if (MODE == 1 && nblk >= 16) {
        Bp = B2 + (size_t)e * Ncols * K2;
        Cout = C2; nb = nblk - 16;
    }
    int n0 = nb * BN;
    int tid = threadIdx.x;

    if (MODE == 1) {
        const int* rowidx = g_list + (size_t)e * NN;
        for (int i = tid; i < BM; i += 256) {
            int gr = mblk * BM + i;
            sidx[i] = (gr < M) ? rowidx[gr] : -1;
        }
        __syncthreads();
    }

    int crow = tid >> 1;
    int cseg = (tid & 1) * 8;
    int asz;
    size_t abase;
    if (MODE == 1) {
        int s = sidx[crow];
        asz = (s >= 0) ? 16 : 0;
        abase = (size_t)(s >= 0 ? s : 0) * K2 + cseg;
    } else {
        int gr = mblk * BM + crow;
        asz = (gr < M) ? 16 : 0;
        abase = ((size_t)e * NN + (gr < M ? gr : 0)) * K2 + cseg;
    }
    size_t bbase = (size_t)(n0 + crow) * K2 + cseg;

    int wid = tid >> 5, lane = tid & 31;
    int g = lane >> 2, tig = lane & 3;
    int wm = wid >> 2, wn = wid & 3;

    u32 aoffL = (u32)((wm * 64 + (lane & 15)) * STR + (lane >> 4) * 4);
    u32 boffL = (u32)((wn * 32 + ((lane >> 4) << 3) + (lane & 7)) * STR + ((lane >> 3) & 1) * 4);

    float acc[4][4][4];
#pragma unroll
    for (int i = 0; i < 4; i++)
#pragma unroll
        for (int j = 0; j < 4; j++)
#pragma unroll
            for (int k = 0; k < 4; k++) acc[i][j][k] = 0.f;

    int KT = K2 / KP;
    int buf = 0;
    u32 sdst = crow * STR + cseg;

    {
        u32* s0 = sm;
        cp_async16z(s0 + 0*ABUF + sdst,     A + abase,      asz);
        cp_async16z(s0 + 0*ABUF + sdst + 4, A + abase + 4,  asz);
        cp_async16z(s0 + 1*ABUF + sdst,     Bp + bbase,     16);
        cp_async16z(s0 + 1*ABUF + sdst + 4, Bp + bbase + 4, 16);
        cp_commit();
    }

    for (int kt = 0; kt < KT; kt++) {
        if (kt + 1 < KT) {
            u32* s1 = sm + (buf ^ 1) * 2 * ABUF;
            size_t ao = abase + (size_t)(kt + 1) * KP;
            size_t bo = bbase + (size_t)(kt + 1) * KP;
            cp_async16z(s1 + 0*ABUF + sdst,     A + ao,      asz);
            cp_async16z(s1 + 0*ABUF + sdst + 4, A + ao + 4,  asz);
            cp_async16z(s1 + 1*ABUF + sdst,     Bp + bo,     16);
            cp_async16z(s1 + 1*ABUF + sdst + 4, Bp + bo + 4, 16);
            cp_commit();
            cp_wait<1>();
        } else {
            cp_wait<0>();
        }
        __syncthreads();

        u32 aA = (u32)__cvta_generic_to_shared(sm + buf * 2 * ABUF);
        u32 aB = aA + ABUF * 4;

#pragma unroll
        for (int ks = 0; ks < 2; ks++) {
            int kb = ks * 8;
            u32 ah[4][4];
#pragma unroll
            for (int mt = 0; mt < 4; mt++) {
                u32 off = (aoffL + mt * 16 * STR + kb) * 4;
                ldsm_x4(ah[mt][0], ah[mt][1], ah[mt][2], ah[mt][3], aA + off);
            }
            u32 bh[4][2];
#pragma unroll
            for (int np = 0; np < 2; np++) {
                u32 off = (boffL + np * 16 * STR + kb) * 4;
                ldsm_x4(bh[2*np][0], bh[2*np][1], bh[2*np+1][0], bh[2*np+1][1], aB + off);
            }
#pragma unroll
            for (int mt = 0; mt < 4; mt++)
#pragma unroll
                for (int nt = 0; nt < 4; nt++)
                    mma_f16(acc[mt][nt], ah[mt], bh[nt]);
        }
        __syncthreads();
        buf ^= 1;
    }

#pragma unroll
    for (int mt = 0; mt < 4; mt++) {
#pragma unroll
        for (int half = 0; half < 2; half++) {
            int lr = wm * 64 + mt * 16 + g + half * 8;
            int gr = mblk * BM + lr;
            if (gr >= M) continue;
            float* orow = Cout + ((size_t)e * NN + gr) * Ncols;
#pragma unroll
            for (int nt = 0; nt < 4; nt++) {
                int col = n0 + wn * 32 + nt * 8 + tig * 2;
                *(float2*)(orow + col) =
                    make_float2(acc[mt][nt][half*2+0], acc[mt][nt][half*2+1]);
            }
        }
    }
}

// ---------------- small projections: Bm, Cm (from x) ----------------
__global__ __launch_bounds__(128)
void proj_small(const float* __restrict__ x, const float* __restrict__ WB,
                const float* __restrict__ WC)
{
    int n = blockIdx.x;
    __shared__ float xs[DD];
    const float* xr = x + (size_t)n * DD;
    for (int i = threadIdx.x; i < DD; i += 128) xs[i] = xr[i];
    __syncthreads();
    int warp = threadIdx.x >> 5, lane = threadIdx.x & 31;
    for (int c = warp; c < 32; c += 4) {
        const float* W; int col; float* out;
        if (c < 16) { W = WB; col = c;      out = g_Bm + (size_t)n * SS + col; }
        else        { W = WC; col = c - 16; out = g_Cm + (size_t)n * SS + col; }
        float s = 0.f;
        for (int k = lane; k < DD; k += 32)
            s = fmaf(xs[k], W[(size_t)k * SS + col], s);
        s += __shfl_xor_sync(~0u, s, 16);
        s += __shfl_xor_sync(~0u, s, 8);
        s += __shfl_xor_sync(~0u, s, 4);
        s += __shfl_xor_sync(~0u, s, 2);
        s += __shfl_xor_sync(~0u, s, 1);
        if (lane == 0) *out = s;
    }
}

// ---------------- selective scan (register partials + smem reduce) -------------
__global__ __launch_bounds__(256)
void scan_kernel(const float* __restrict__ x, const float* __restrict__ A_log,
                 const float* __restrict__ D_param)
{
    int b = blockIdx.x >> 6;
    int dchunk = blockIdx.x & 63;
    int dl = threadIdx.x >> 4;      // d-local 0..15
    int s  = threadIdx.x & 15;      // state index
    int d = dchunk * 16 + dl;

    float A_ds = -__expf(A_log[d * SS + s]);

    __shared__ float sx[16][16], sd[16][16];
    __shared__ float sB[16][17], sC[16][17];
    __shared__ float sp[16 * 272];  // [q][s*17 + dl]
    __shared__ float sDp[16];

    int tt = threadIdx.x >> 4;
    int cc = threadIdx.x & 15;
    const int base_bt = b * LL;

    if (threadIdx.x < 16) sDp[threadIdx.x] = D_param[dchunk * 16 + threadIdx.x];

    size_t xoff = ((size_t)(base_bt + tt)) * DD + dchunk * 16 + cc;
    float rx = x[xoff];
    float rd = g_delta[xoff];
    size_t boff = ((size_t)(base_bt + tt)) * SS + cc;
    float rB = g_Bm[boff];
    float rC = g_Cm[boff];

    float h = 0.f;
    for (int t0 = 0; t0 < LL; t0 += 16) {
        __syncthreads();
        sx[tt][cc] = rx; sd[tt][cc] = rd; sB[tt][cc] = rB; sC[tt][cc] = rC;
        __syncthreads();
        if (t0 + 16 < LL) {
            size_t xo = ((size_t)(base_bt + t0 + 16 + tt)) * DD + dchunk * 16 + cc;
            rx = x[xo]; rd = g_delta[xo];
            size_t bo = ((size_t)(base_bt + t0 + 16 + tt)) * SS + cc;
            rB = g_Bm[bo]; rC = g_Cm[bo];
        }
        float p[16];
#pragma unroll
        for (int q = 0; q < 16; q++) {
            float xv = sx[q][dl], dv = sd[q][dl];
            float Bv = sB[q][s],  Cv = sC[q][s];
            float a  = __expf(fminf(dv * A_ds, 10.f));
            float bBc = fminf(fmaxf(dv * Bv, -10.f), 10.f);
            h = fminf(fmaxf(a * h + bBc * xv, -10000.f), 10000.f);
            p[q] = h * Cv;
        }
#pragma unroll
        for (int q = 0; q < 16; q++)
            sp[q * 272 + s * 17 + dl] = p[q];
        __syncthreads();
        // reduction role: (q2 = tt, d2 = cc)
        float ysum = 0.f;
#pragma unroll
        for (int s2 = 0; s2 < 16; s2++)
            ysum += sp[tt * 272 + s2 * 17 + cc];
        float y = fmaf(sx[tt][cc], sDp[cc], ysum);
        size_t yo = ((size_t)(base_bt + t0 + tt)) * DD + dchunk * 16 + cc;
        g_ssm[yo] = y;
        float yn = __shfl_down_sync(~0u, y, 1);
        if (!(cc & 1)) {
            float ya = fminf(fmaxf(y,  -60000.f), 60000.f);
            float yb = fminf(fmaxf(yn, -60000.f), 60000.f);
            size_t po = ((size_t)(base_bt + t0 + tt)) * (DD/2) + dchunk * 8 + (cc >> 1);
            g_sF[po] = pack_h2(ya, yb);
        }
    }
}

// ---------------- router on SSM output: softmax, top-2, expert lists ----------
__global__ __launch_bounds__(128)
void router_kernel(const float* __restrict__ WR)
{
    int n = blockIdx.x;
    __shared__ float xs[DD];
    __shared__ float logits[EE];
    const float* xr = g_ssm + (size_t)n * DD;
    for (int i = threadIdx.x; i < DD; i += 128) xs[i] = xr[i];
    __syncthreads();
    int warp = threadIdx.x >> 5, lane = threadIdx.x & 31;
    {
        float s = 0.f;
        for (int k = lane; k < DD; k += 32)
            s = fmaf(xs[k], WR[(size_t)k * EE + warp], s);
        s += __shfl_xor_sync(~0u, s, 16);
        s += __shfl_xor_sync(~0u, s, 8);
        s += __shfl_xor_sync(~0u, s, 4);
        s += __shfl_xor_sync(~0u, s, 2);
        s += __shfl_xor_sync(~0u, s, 1);
        if (lane == 0) logits[warp] = s;
    }
    __syncthreads();
    if (threadIdx.x == 0) {
        float l[4] = {logits[0], logits[1], logits[2], logits[3]};
        float m = fmaxf(fmaxf(l[0], l[1]), fmaxf(l[2], l[3]));
        float e[4], sum = 0.f;
#pragma unroll
        for (int i = 0; i < 4; i++) { e[i] = __expf(l[i] - m); sum += e[i]; }
        float p[4];
#pragma unroll
        for (int i = 0; i < 4; i++) p[i] = e[i] / sum;
        int i0 = 0;
#pragma unroll
        for (int i = 1; i < 4; i++) if (p[i] > p[i0]) i0 = i;
        int i1 = -1;
#pragma unroll
        for (int i = 0; i < 4; i++) {
            if (i == i0) continue;
            if (i1 < 0 || p[i] > p[i1]) i1 = i;
        }
        float w0 = p[i0], w1 = p[i1];
        float sw = w0 + w1 + 1e-9f;
        w0 /= sw; w1 /= sw;
        int pos = atomicAdd(&g_cnt[i0], 1);
        g_list[i0*NN + pos] = n; g_cw[i0*NN + pos] = w0;
        g_loc[n] = i0 * NN + pos;
        pos = atomicAdd(&g_cnt[i1], 1);
        g_list[i1*NN + pos] = n; g_cw[i1*NN + pos] = w1;
        g_loc[NN + n] = i1 * NN + pos;
    }
}

// ---------------- silu(G)*U -> rmsnorm(wn) -> * cw (fp16 output), batched -----
__global__ __launch_bounds__(256)
void act_norm(const float* __restrict__ wn_all)
{
    int i = blockIdx.x;
    int e = blockIdx.y;
    if (i >= g_cnt[e]) return;
    size_t row = (size_t)e * NN + i;
    const float* wn = wn_all + (size_t)e * HH;
    __shared__ float buf[HH];
    __shared__ float red[8];
    float ss = 0.f;
    for (int j = threadIdx.x; j < HH; j += 256) {
        float g = g_G[row * HH + j];
        float u = g_U[row * HH + j];
        float v = (g / (1.f + __expf(-g))) * u;
        buf[j] = v;
        ss = fmaf(v, v, ss);
    }
    ss += __shfl_xor_sync(~0u, ss, 16);
    ss += __shfl_xor_sync(~0u, ss, 8);
    ss += __shfl_xor_sync(~0u, ss, 4);
    ss += __shfl_xor_sync(~0u, ss, 2);
    ss += __shfl_xor_sync(~0u, ss, 1);
    if ((threadIdx.x & 31) == 0) red[threadIdx.x >> 5] = ss;
    __syncthreads();
    if (threadIdx.x < 32) {
        float v = (threadIdx.x < 8) ? red[threadIdx.x] : 0.f;
        v += __shfl_xor_sync(~0u, v, 4);
        v += __shfl_xor_sync(~0u, v, 2);
        v += __shfl_xor_sync(~0u, v, 1);
        if (threadIdx.x == 0) red[0] = v;
    }
    __syncthreads();
    float scale = g_cw[(size_t)e * NN + i] * rsqrtf(red[0] / (float)HH + 1e-6f);
    for (int j2 = threadIdx.x; j2 < HH / 2; j2 += 256) {
        float v0 = wn[2 * j2]     * buf[2 * j2]     * scale;
        float v1 = wn[2 * j2 + 1] * buf[2 * j2 + 1] * scale;
        g_aF[row * (HH/2) + j2] = pack_h2(v0, v1);
    }
}

// ---------------- final rmsnorm over (ssm + Dn[loc0] + Dn[loc1]) --------------
__global__ __launch_bounds__(256)
void final_norm(const float* __restrict__ norm_w, float* __restrict__ out)
{
    int n = blockIdx.x;
    __shared__ float red[8];
    __shared__ float buf[DD];
    int l0 = g_loc[n], l1 = g_loc[NN + n];
    const float* r0 = g_Dn + (size_t)l0 * DD;
    const float* r1 = g_Dn + (size_t)l1 * DD;
    const float* rs = g_ssm + (size_t)n * DD;
    float ss = 0.f;
    for (int j = threadIdx.x; j < DD; j += 256) {
        float v = rs[j] + r0[j] + r1[j];
        buf[j] = v;
        ss = fmaf(v, v, ss);
    }
    ss += __shfl_xor_sync(~0u, ss, 16);
    ss += __shfl_xor_sync(~0u, ss, 8);
    ss += __shfl_xor_sync(~0u, ss, 4);
    ss += __shfl_xor_sync(~0u, ss, 2);
    ss += __shfl_xor_sync(~0u, ss, 1);
    if ((threadIdx.x & 31) == 0) red[threadIdx.x >> 5] = ss;
    __syncthreads();
    if (threadIdx.x < 32) {
        float v = (threadIdx.x < 8) ? red[threadIdx.x] : 0.f;
        v += __shfl_xor_sync(~0u, v, 4);
        v += __shfl_xor_sync(~0u, v, 2);
        v += __shfl_xor_sync(~0u, v, 1);
        if (threadIdx.x == 0) red[0] = v;
    }
    __syncthreads();
    float inv = rsqrtf(red[0] / (float)DD + 1e-6f);
    for (int j = threadIdx.x; j < DD; j += 256)
        out[(size_t)n * DD + j] = norm_w[j] * buf[j] * inv;
}

// ---------------- launch ----------------
extern "C" void kernel_launch(void* const* d_in, const int* in_sizes, int n_in,
                              void* d_out, int out_size)
{
    const float* x        = (const float*)d_in[0];
    const float* A_log    = (const float*)d_in[1];
    const float* D_param  = (const float*)d_in[2];
    const float* W_delta  = (const float*)d_in[3];
    const float* b_delta  = (const float*)d_in[4];
    const float* W_B      = (const float*)d_in[5];
    const float* W_C      = (const float*)d_in[6];
    const float* W_router = (const float*)d_in[7];
    const float* Wg       = (const float*)d_in[8];
    const float* Wu       = (const float*)d_in[9];
    const float* Wd       = (const float*)d_in[10];
    const float* wn_exp   = (const float*)d_in[11];
    const float* norm_w   = (const float*)d_in[12];
    float* out = (float*)d_out;

    float *p_delta, *p_G, *p_U, *p_Dn;
    u32 *p_xHi, *p_xLo, *p_sF, *p_aF;
    u32 *p_WdHi, *p_WdLo, *p_WgF, *p_WuF, *p_WnF;
    cudaGetSymbolAddress((void**)&p_delta, g_delta);
    cudaGetSymbolAddress((void**)&p_G,     g_G);
    cudaGetSymbolAddress((void**)&p_U,     g_U);
    cudaGetSymbolAddress((void**)&p_Dn,    g_Dn);
    cudaGetSymbolAddress((void**)&p_xHi,   g_xHi);
    cudaGetSymbolAddress((void**)&p_xLo,   g_xLo);
    cudaGetSymbolAddress((void**)&p_sF,    g_sF);
    cudaGetSymbolAddress((void**)&p_aF,    g_aF);
    cudaGetSymbolAddress((void**)&p_WdHi,  g_WdHi);
    cudaGetSymbolAddress((void**)&p_WdLo,  g_WdLo);
    cudaGetSymbolAddress((void**)&p_WgF,   g_WgF);
    cudaGetSymbolAddress((void**)&p_WuF,   g_WuF);
    cudaGetSymbolAddress((void**)&p_WnF,   g_WnF);

    cudaFuncSetAttribute(gemm_bf,    cudaFuncAttributeMaxDynamicSharedMemorySize, GEMM_SMEM_BYTES);
    cudaFuncSetAttribute(gemm_hf<1>, cudaFuncAttributeMaxDynamicSharedMemorySize, GEMMH_SMEM_BYTES);
    cudaFuncSetAttribute(gemm_hf<2>, cudaFuncAttributeMaxDynamicSharedMemorySize, GEMMH_SMEM_BYTES);

    zero_counts<<<1, 32>>>();

    // operand pre-conversion
    {
        int n2 = NN * DD / 2;
        split_x_kernel<<<(n2 + 255) / 256, 256>>>(x, p_xHi, p_xLo, n2);
    }
    {
        dim3 blk(32, 8);
        dim3 gWdel(DD/2/32, DD/32, 1);
        split_w_kernel<<<gWdel, blk>>>(W_delta, p_WdHi, p_WdLo, DD, DD);
        dim3 gUp(DD/2/32, HH/32, EE);
        split_w_h_kernel<<<gUp, blk>>>(Wg, p_WgF, DD, HH);
        split_w_h_kernel<<<gUp, blk>>>(Wu, p_WuF, DD, HH);
        dim3 gDn(HH/2/32, DD/32, EE);
        split_w_h_kernel<<<gDn, blk>>>(Wd, p_WnF, HH, DD);
    }

    // delta = softplus(x @ W_delta + b)   [bf16x2 3-pass]
    {
        dim3 grid(DD / BN, NN / BM);
        gemm_bf<<<grid, 256, GEMM_SMEM_BYTES>>>(
            p_xHi, p_xLo, p_WdHi, p_WdLo, p_delta, b_delta, NN, DD, DD);
    }

    // Bm, Cm from x
    proj_small<<<NN, 128>>>(x, W_B, W_C);

    // selective scan -> g_ssm / fp16 ssm
    scan_kernel<<<BB * (DD / 16), 256>>>(x, A_log, D_param);

    // router on SSM output
    router_kernel<<<NN, 128>>>(W_router);

    // MoE, all experts batched:
    // G/U = gather(ssm) @ {Wg,Wu}   [fp16 single-pass, z = expert]
    gemm_hf<1><<<dim3(2 * HH / BN, NN / BM, EE), 256, GEMMH_SMEM_BYTES>>>(
        p_sF, p_WgF, p_WuF, p_G, p_U, HH, DD);
    // act = wn * rmsnorm(silu(G)*U) * cw  (fp16 output)
    act_norm<<<dim3(NN, EE), 256>>>(wn_exp);
    // Dn[e][i] = act @ Wd_e   [fp16 single-pass, compact store]
    gemm_hf<2><<<dim3(DD / BN, NN / BM, EE), 256, GEMMH_SMEM_BYTES>>>(
        p_aF, p_WnF, nullptr, p_Dn, nullptr, DD, HH);

    // out = rmsnorm(ssm + Dn[loc0] + Dn[loc1], norm_w)
    final_norm<<<NN, 256>>>(norm_w, out);
}